// round 11
// baseline (speedup 1.0000x reference)
#include <cuda_runtime.h>
#include <math.h>

#define B_ 512
#define T_ 256
#define N_ 128
#define M_ 256
#define FM_ 1024   // 4*M
#define GRID_LSTM 128

// ---------------- scratch (device globals: allocation-free) ----------------
__device__ float g_r2[(size_t)B_ * N_ * T_];            // [b][n][u]       67 MB
__device__ float g_Xk[(size_t)T_ * B_ * FM_];           // [t][b][4M]     537 MB
__device__ float g_H[(size_t)(T_ + 1) * B_ * M_];       // row-layout hist 135 MB
__device__ float g_S[(size_t)(T_ + 1) * B_ * M_];       // row-layout hist 135 MB
__device__ float g_Ht[(size_t)(T_ + 1) * 16 * M_ * 32]; // [t][bx][m][r]  135 MB
__device__ float g_R1[(size_t)T_ * B_ * T_];            // [tau][b][u]    134 MB
__device__ float g_Wrt[(size_t)M_ * FM_];               // Wr [k][m][gate]  1 MB

// per-bx-group arrival counters (zeroed by k_init each launch -> replay-safe)
__device__ unsigned long long g_arr[16];

__device__ __forceinline__ float sigm(float x) {
    return __fdividef(1.0f, 1.0f + __expf(-x));
}
// accurate tanh (chain): rel err ~1e-6
__device__ __forceinline__ float tanh_e(float x) {
    float a = fabsf(x);
    float e = __expf(-2.0f * a);
    float r = __fdividef(1.0f - e, 1.0f + e);
    return copysignf(r, x);
}
// HW tanh (attention logits only)
__device__ __forceinline__ float tanh_fast(float x) {
    float y;
    asm("tanh.approx.f32 %0, %1;" : "=f"(y) : "f"(x));
    return y;
}

// ---- packed f32x2 helpers (FFMA2: B300, PTX-only path) ----
__device__ __forceinline__ unsigned long long fma2(unsigned long long a,
                                                   unsigned long long b,
                                                   unsigned long long c) {
    unsigned long long d;
    asm("fma.rn.f32x2 %0, %1, %2, %3;" : "=l"(d) : "l"(a), "l"(b), "l"(c));
    return d;
}
__device__ __forceinline__ unsigned long long add2(unsigned long long a,
                                                   unsigned long long b) {
    unsigned long long d;
    asm("add.rn.f32x2 %0, %1, %2;" : "=l"(d) : "l"(a), "l"(b));
    return d;
}
__device__ __forceinline__ unsigned long long dup2(float x) {
    unsigned long long r;
    asm("mov.b64 %0, {%1, %1};" : "=l"(r) : "f"(x));
    return r;
}
__device__ __forceinline__ void unpack2(unsigned long long p, float& lo, float& hi) {
    asm("mov.b64 {%0, %1}, %2;" : "=f"(lo), "=f"(hi) : "l"(p));
}

// ---- init: slot 0 <- (h, s) in both layouts; Wr gate-interleave; reset bars ----
__global__ void k_init(const float* __restrict__ s, const float* __restrict__ h,
                       const float* __restrict__ Wr) {
    int i = blockIdx.x * blockDim.x + threadIdx.x;
    if (i < B_ * M_) {
        g_H[i] = h[i];
        g_S[i] = s[i];
        int b = i >> 8;       // row
        int m = i & 255;      // col
        int bx = b >> 5, r = b & 31;
        g_Ht[((size_t)bx * 256 + m) * 32 + r] = h[i];
    }
    if (i < M_ * FM_) {
        int k = i >> 10;
        int c = i & 1023;
        int g = c >> 8;       // gate 0..3 (i,f,c,o)
        int m = c & 255;
        g_Wrt[((size_t)(k * 256 + m)) * 4 + g] = Wr[i];
    }
    if (i < 16) g_arr[i] = 0ull;
}

// ---- r2[b][n][u] = sum_t x[b][t][n] * Ue[t][u] ----
__global__ __launch_bounds__(256) void k_r2(const float* __restrict__ x,
                                            const float* __restrict__ Ue) {
    int b = blockIdx.x;
    int ut = blockIdx.y * 64;
    __shared__ float xs[32][128];
    __shared__ float us[32][64];
    int tid = threadIdx.x;
    int n0 = (tid & 31) * 4;
    int u0 = (tid >> 5) * 8;

    float acc[8][4];
#pragma unroll
    for (int j = 0; j < 8; j++)
#pragma unroll
        for (int i = 0; i < 4; i++) acc[j][i] = 0.f;

    for (int kt = 0; kt < T_; kt += 32) {
#pragma unroll
        for (int l = 0; l < 4; l++) {
            int idx = l * 256 + tid;
            int t = idx >> 5, n4 = idx & 31;
            *(float4*)&xs[t][n4 * 4] =
                ((const float4*)x)[(size_t)(b * T_ + kt + t) * 32 + n4];
        }
#pragma unroll
        for (int l = 0; l < 2; l++) {
            int idx = l * 256 + tid;
            int t = idx >> 4, u4 = idx & 15;
            *(float4*)&us[t][u4 * 4] =
                ((const float4*)Ue)[(size_t)(kt + t) * 64 + (ut >> 2) + u4];
        }
        __syncthreads();
#pragma unroll 8
        for (int k = 0; k < 32; k++) {
            float4 x4 = *(const float4*)&xs[k][n0];
            float4 ua = *(const float4*)&us[k][u0];
            float4 ub = *(const float4*)&us[k][u0 + 4];
            float xv[4] = {x4.x, x4.y, x4.z, x4.w};
            float uu[8] = {ua.x, ua.y, ua.z, ua.w, ub.x, ub.y, ub.z, ub.w};
#pragma unroll
            for (int j = 0; j < 8; j++)
#pragma unroll
                for (int i = 0; i < 4; i++) acc[j][i] += xv[i] * uu[j];
        }
        __syncthreads();
    }
#pragma unroll
    for (int i = 0; i < 4; i++) {
        size_t base = ((size_t)(b * N_ + n0 + i)) * T_ + ut + u0;
        *(float4*)&g_r2[base] = make_float4(acc[0][i], acc[1][i], acc[2][i], acc[3][i]);
        *(float4*)&g_r2[base + 4] = make_float4(acc[4][i], acc[5][i], acc[6][i], acc[7][i]);
    }
}

// ---- Xk[t][b][c] = x[b][t][:] @ Wk[:,c] + bias[c]  (FFMA2) ----
__global__ __launch_bounds__(256) void k_xk(const float* __restrict__ x,
                                            const float* __restrict__ Wk,
                                            const float* __restrict__ bias) {
    int rb = blockIdx.x;
    int tid = threadIdx.x;
    int c0 = blockIdx.y * 256 + (tid & 63) * 4;
    int rt = tid >> 6;
    __shared__ float as[32][128];
#pragma unroll
    for (int l = 0; l < 4; l++) {
        int idx = l * 256 + tid;
        int r = idx >> 5, n4 = idx & 31;
        *(float4*)&as[r][n4 * 4] =
            ((const float4*)x)[(size_t)(rb * 32 + r) * 32 + n4];
    }
    __syncthreads();
    unsigned long long acc[8][2];
#pragma unroll
    for (int i = 0; i < 8; i++) { acc[i][0] = 0ull; acc[i][1] = 0ull; }
#pragma unroll 4
    for (int k = 0; k < 128; k++) {
        ulonglong2 wv = *(const ulonglong2*)&Wk[(size_t)k * 1024 + c0];
#pragma unroll
        for (int i = 0; i < 8; i++) {
            unsigned long long a2 = dup2(as[rt * 8 + i][k]);
            acc[i][0] = fma2(a2, wv.x, acc[i][0]);
            acc[i][1] = fma2(a2, wv.y, acc[i][1]);
        }
    }
    float4 bv = ((const float4*)bias)[c0 >> 2];
#pragma unroll
    for (int i = 0; i < 8; i++) {
        int rbt = rb * 32 + rt * 8 + i;
        int b = rbt >> 8;
        int t = rbt & 255;
        float v0, v1, v2, v3;
        unpack2(acc[i][0], v0, v1);
        unpack2(acc[i][1], v2, v3);
        float4 v = make_float4(v0 + bv.x, v1 + bv.y, v2 + bv.z, v3 + bv.w);
        ((float4*)g_Xk)[((size_t)t * B_ + b) * 256 + (c0 >> 2)] = v;
    }
}

// ---- persistent LSTM v3: 8 rows/thread, k-quartered, dup'd H pairs ----
// grid 128 = 16 bx (32 rows) x 8 by (32 m). block 512 = warp(rw 0..3, kq 0..3).
// smem: ws 128KB (Wr slice) + hd 64KB (H pairs, overlaid by partial buffer).
__global__ __launch_bounds__(512, 1) void k_lstm_all() {
    extern __shared__ char smc[];
    float* ws = (float*)smc;                                      // [k][32m][4g]
    unsigned long long* hd = (unsigned long long*)(smc + 131072); // [k][r] (h,h)
    unsigned long long* pp = hd;                                  // partial overlay
    const ulonglong2* wsv = (const ulonglong2*)ws;
    const ulonglong2* hdv2 = (const ulonglong2*)hd;

    int tid = threadIdx.x;
    int bx = blockIdx.x >> 3;   // barrier group (rows bx*32..+31)
    int by = blockIdx.x & 7;    // m cols by*32..+31
    int ml = tid & 31;
    int mg = by * 32 + ml;
    int warp = tid >> 5;
    int rw = warp & 3;          // row group: rows rw*8..+7
    int kq = warp >> 2;         // k quarter: k in [kq*64, +64)
    int r0 = rw * 8 + kq * 2;   // my 2 epilogue rows (local 0..31)

    // weights into smem (once)
#pragma unroll
    for (int l = 0; l < 16; l++) {
        int f = l * 512 + tid;
        int k = f >> 5, mm = f & 31;
        ((float4*)ws)[f] = ((const float4*)g_Wrt)[(size_t)k * 256 + by * 32 + mm];
    }

    // s carry + first Xk prefetch for my 2 rows
    float s2[2];
    float px[2][4];
#pragma unroll
    for (int i = 0; i < 2; i++) {
        int b = bx * 32 + r0 + i;
        s2[i] = g_S[(size_t)b * M_ + mg];
        size_t xo = (size_t)b * FM_ + mg;
        px[i][0] = g_Xk[xo];
        px[i][1] = g_Xk[xo + 256];
        px[i][2] = g_Xk[xo + 512];
        px[i][3] = g_Xk[xo + 768];
    }
    // stage hd[0]: duplicated pairs from g_Ht[0][bx] ([m][r] floats)
#pragma unroll
    for (int l = 0; l < 4; l++) {
        int f = l * 512 + tid;            // f = m*8 + rq
        float4 v = ((const float4*)g_Ht)[(size_t)bx * 2048 + f];
        int p = f * 4;                    // pair base = m*32 + rq*4
        hd[p + 0] = dup2(v.x);
        hd[p + 1] = dup2(v.y);
        hd[p + 2] = dup2(v.z);
        hd[p + 3] = dup2(v.w);
    }
    __syncthreads();

    for (int t = 0; t < T_; t++) {
        unsigned long long aif[8], ago[8];
#pragma unroll
        for (int i = 0; i < 8; i++) { aif[i] = 0ull; ago[i] = 0ull; }

        int kb = kq * 64;
#pragma unroll 4
        for (int kk = 0; kk < 64; kk++) {
            int k = kb + kk;
            ulonglong2 wv = wsv[k * 32 + ml];          // (wi,wf),(wg,wo)
            ulonglong2 h01 = hdv2[k * 16 + rw * 4 + 0]; // rows rw*8+0,1 (dup'd)
            ulonglong2 h23 = hdv2[k * 16 + rw * 4 + 1];
            ulonglong2 h45 = hdv2[k * 16 + rw * 4 + 2];
            ulonglong2 h67 = hdv2[k * 16 + rw * 4 + 3];
            aif[0] = fma2(h01.x, wv.x, aif[0]);  ago[0] = fma2(h01.x, wv.y, ago[0]);
            aif[1] = fma2(h01.y, wv.x, aif[1]);  ago[1] = fma2(h01.y, wv.y, ago[1]);
            aif[2] = fma2(h23.x, wv.x, aif[2]);  ago[2] = fma2(h23.x, wv.y, ago[2]);
            aif[3] = fma2(h23.y, wv.x, aif[3]);  ago[3] = fma2(h23.y, wv.y, ago[3]);
            aif[4] = fma2(h45.x, wv.x, aif[4]);  ago[4] = fma2(h45.x, wv.y, ago[4]);
            aif[5] = fma2(h45.y, wv.x, aif[5]);  ago[5] = fma2(h45.y, wv.y, ago[5]);
            aif[6] = fma2(h67.x, wv.x, aif[6]);  ago[6] = fma2(h67.x, wv.y, ago[6]);
            aif[7] = fma2(h67.y, wv.x, aif[7]);  ago[7] = fma2(h67.y, wv.y, ago[7]);
        }
        __syncthreads();   // all hd reads done before partial overlay writes

        // store partials for the 6 rows I don't own (slot-major: conflict-free)
#pragma unroll
        for (int i = 0; i < 8; i++) {
            int owner = i >> 1;
            if (kq != owner) {
                int cidx = kq - (kq > owner ? 1 : 0);   // 0..2
                int sf = (i * 3 + cidx) * 2;
                pp[(size_t)sf * 128 + rw * 32 + ml] = aif[i];
                pp[(size_t)(sf + 1) * 128 + rw * 32 + ml] = ago[i];
            }
        }
        __syncthreads();

        // combine + epilogue for my 2 rows
        float hv[2];
#pragma unroll
        for (int ii = 0; ii < 2; ii++) {
            int i = kq * 2 + ii;
            unsigned long long zif = aif[i], zgo = ago[i];
#pragma unroll
            for (int c = 0; c < 3; c++) {
                int sf = (i * 3 + c) * 2;
                zif = add2(zif, pp[(size_t)sf * 128 + rw * 32 + ml]);
                zgo = add2(zgo, pp[(size_t)(sf + 1) * 128 + rw * 32 + ml]);
            }
            float zi, zf, zg, zo;
            unpack2(zif, zi, zf);
            unpack2(zgo, zg, zo);
            zi += px[ii][0];
            zf += px[ii][1];
            zg += px[ii][2];
            zo += px[ii][3];
            float ig = sigm(zi), fg = sigm(zf), og = sigm(zo);
            float gg = tanh_e(zg);
            float sn = fg * s2[ii] + ig * gg;
            float hn = og * tanh_e(sn);
            s2[ii] = sn;
            hv[ii] = hn;
            int b = bx * 32 + r0 + ii;
            size_t dn = ((size_t)(t + 1) * B_ + b) * M_ + mg;
            g_S[dn] = sn;
            g_H[dn] = hn;
        }
        // transposed store: g_Ht[t+1][bx][mg][r0..r0+1]
        *(float2*)&g_Ht[((((size_t)(t + 1) * 16 + bx) * 256 + mg)) * 32 + r0] =
            make_float2(hv[0], hv[1]);
        // prefetch next step's Xk (lands during spin/stage)
        int tn = (t < T_ - 1) ? t + 1 : t;
#pragma unroll
        for (int ii = 0; ii < 2; ii++) {
            int b = bx * 32 + r0 + ii;
            size_t xo = ((size_t)tn * B_ + b) * FM_ + mg;
            px[ii][0] = g_Xk[xo];
            px[ii][1] = g_Xk[xo + 256];
            px[ii][2] = g_Xk[xo + 512];
            px[ii][3] = g_Xk[xo + 768];
        }
        __syncthreads();   // all stores + pp reads done before arrive/overlay reuse

        if (tid == 0) {
            __threadfence();
            atomicAdd(&g_arr[bx], 1ull);
        }
        unsigned long long tgt = 8ull * (unsigned long long)(t + 1);
        while (*((volatile unsigned long long*)&g_arr[bx]) < tgt) {}

        // restage hd from g_Ht[t+1][bx]
#pragma unroll
        for (int l = 0; l < 4; l++) {
            int f = l * 512 + tid;
            float4 v = ((const float4*)g_Ht)[((size_t)(t + 1) * 16 + bx) * 2048 + f];
            int p = f * 4;
            hd[p + 0] = dup2(v.x);
            hd[p + 1] = dup2(v.y);
            hd[p + 2] = dup2(v.z);
            hd[p + 3] = dup2(v.w);
        }
        __syncthreads();
    }
}

// ---- R1[tau][b][u] = concat(H,S)[tau][b] @ We[:,u]  (FFMA2) ----
__global__ __launch_bounds__(256) void k_R1(const float* __restrict__ We) {
    int rb = blockIdx.x;
    int tid = threadIdx.x;
    int u0 = (tid & 63) * 4;
    int rt = tid >> 6;
    __shared__ float as[32][64];
    unsigned long long acc[8][2];
#pragma unroll
    for (int i = 0; i < 8; i++) { acc[i][0] = 0ull; acc[i][1] = 0ull; }

    for (int ch = 0; ch < 8; ch++) {
        const float* src = (ch < 4) ? g_H : g_S;
        int boff = (ch & 3) * 16;
        __syncthreads();
#pragma unroll
        for (int l = 0; l < 2; l++) {
            int idx = l * 256 + tid;
            int r = idx >> 4, j4 = idx & 15;
            *(float4*)&as[r][j4 * 4] =
                ((const float4*)src)[(size_t)(rb * 32 + r) * 64 + boff + j4];
        }
        __syncthreads();
#pragma unroll 4
        for (int kk = 0; kk < 64; kk++) {
            ulonglong2 wv = *(const ulonglong2*)&We[(size_t)(ch * 64 + kk) * 256 + u0];
#pragma unroll
            for (int i = 0; i < 8; i++) {
                unsigned long long a2 = dup2(as[rt * 8 + i][kk]);
                acc[i][0] = fma2(a2, wv.x, acc[i][0]);
                acc[i][1] = fma2(a2, wv.y, acc[i][1]);
            }
        }
    }
#pragma unroll
    for (int i = 0; i < 8; i++) {
        float v0, v1, v2, v3;
        unpack2(acc[i][0], v0, v1);
        unpack2(acc[i][1], v2, v3);
        ((float4*)g_R1)[(size_t)(rb * 32 + rt * 8 + i) * 64 + (u0 >> 2)] =
            make_float4(v0, v1, v2, v3);
    }
}

// ---- fused: e = tanh(R1 + r2) @ ve ; softmax over n ; out = alpha * x ----
__global__ __launch_bounds__(512) void k_e(const float* __restrict__ x,
                                           const float* __restrict__ ve,
                                           float* __restrict__ out) {
    extern __shared__ float r2s[];   // 128 * 260 floats
    __shared__ float r1s[4][256];
    __shared__ float ves[256];
    __shared__ float redm[16];
    __shared__ float reds[16];
    int b = blockIdx.x;
    int tau0 = blockIdx.y * 32;
    int tid = threadIdx.x;
    int lane = tid & 31;
    int warp = tid >> 5;
    int q = tid >> 7;
    int n = tid & 127;

    if (tid < 256) ves[tid] = ve[tid];
#pragma unroll
    for (int l = 0; l < 16; l++) {
        int idx = l * 512 + tid;
        int nn = idx >> 6, u4 = idx & 63;
        float4 v = ((const float4*)g_r2)[(size_t)(b * N_ + nn) * 64 + u4];
        *(float4*)&r2s[nn * 260 + u4 * 4] = v;
    }
    __syncthreads();
    const float* rp = &r2s[n * 260];

    for (int ti = 0; ti < 8; ti++) {
#pragma unroll
        for (int l = 0; l < 2; l++) {
            int idx = l * 512 + tid;
            int wh = idx >> 8, u = idx & 255;
            r1s[wh][u] = g_R1[((size_t)(tau0 + ti * 4 + wh) * B_ + b) * T_ + u];
        }
        __syncthreads();
        const float* r1p = r1s[q];
        float acc0 = 0.f, acc1 = 0.f;
#pragma unroll 4
        for (int u4 = 0; u4 < 64; u4++) {
            float4 rv = *(const float4*)&rp[u4 * 4];
            float4 r1 = *(const float4*)&r1p[u4 * 4];
            float4 vv = *(const float4*)&ves[u4 * 4];
            acc0 += tanh_fast(r1.x + rv.x) * vv.x;
            acc1 += tanh_fast(r1.y + rv.y) * vv.y;
            acc0 += tanh_fast(r1.z + rv.z) * vv.z;
            acc1 += tanh_fast(r1.w + rv.w) * vv.w;
        }
        float e = acc0 + acc1;

        float mx = e;
#pragma unroll
        for (int off = 16; off >= 1; off >>= 1)
            mx = fmaxf(mx, __shfl_xor_sync(0xffffffffu, mx, off));
        if (lane == 0) redm[warp] = mx;
        __syncthreads();
        mx = fmaxf(fmaxf(redm[q * 4], redm[q * 4 + 1]),
                   fmaxf(redm[q * 4 + 2], redm[q * 4 + 3]));
        float ex = __expf(e - mx);
        float sm = ex;
#pragma unroll
        for (int off = 16; off >= 1; off >>= 1)
            sm += __shfl_xor_sync(0xffffffffu, sm, off);
        if (lane == 0) reds[warp] = sm;
        __syncthreads();
        sm = reds[q * 4] + reds[q * 4 + 1] + reds[q * 4 + 2] + reds[q * 4 + 3];
        float alpha = ex / sm;

        int tau = tau0 + ti * 4 + q;
        size_t oi = ((size_t)b * T_ + tau) * N_ + n;
        out[oi] = alpha * x[oi];
        __syncthreads();
    }
}

extern "C" void kernel_launch(void* const* d_in, const int* in_sizes, int n_in,
                              void* d_out, int out_size) {
    const float* x  = (const float*)d_in[0];
    const float* s  = (const float*)d_in[1];
    const float* h  = (const float*)d_in[2];
    const float* We = (const float*)d_in[3];
    const float* Ue = (const float*)d_in[4];
    const float* ve = (const float*)d_in[5];
    const float* Wk = (const float*)d_in[6];
    const float* Wr = (const float*)d_in[7];
    const float* bb = (const float*)d_in[8];
    float* out = (float*)d_out;
    (void)in_sizes; (void)n_in; (void)out_size;

    k_init<<<1024, 256>>>(s, h, Wr);
    k_r2<<<dim3(B_, 4), 256>>>(x, Ue);
    k_xk<<<dim3(4096, 4), 256>>>(x, Wk, bb);

    const int SML = 131072 + 65536;  // 128KB weights + 64KB dup'd H / partials
    cudaFuncSetAttribute(k_lstm_all, cudaFuncAttributeMaxDynamicSharedMemorySize, SML);
    k_lstm_all<<<GRID_LSTM, 512, SML>>>();

    k_R1<<<4096, 256>>>(We);

    const int SME = 128 * 260 * (int)sizeof(float);
    cudaFuncSetAttribute(k_e, cudaFuncAttributeMaxDynamicSharedMemorySize, SME);
    k_e<<<dim3(B_, 8), 512, SME>>>(x, ve, out);
}

// round 13
// speedup vs baseline: 1.2619x; 1.2619x over previous
#include <cuda_runtime.h>
#include <cuda_bf16.h>
#include <math.h>
#include <stdint.h>

#define B_ 512
#define T_ 256
#define N_ 128
#define M_ 256
#define FM_ 1024
#define GRID_LSTM 128

__device__ float g_r2[(size_t)B_ * N_ * T_];
__device__ float g_Xk[(size_t)T_ * B_ * FM_];
__device__ float g_H[(size_t)(T_ + 1) * B_ * M_];
__device__ float g_S[(size_t)(T_ + 1) * B_ * M_];
__device__ float g_Ht[(size_t)(T_ + 1) * 16 * M_ * 32];
__device__ float g_R1[(size_t)T_ * B_ * T_];
__device__ float g_Wrt[(size_t)M_ * FM_];
__device__ unsigned long long g_arr[16];

__device__ __align__(16) __nv_bfloat16 g_xs_hi[(size_t)B_ * T_ * N_];
__device__ __align__(16) __nv_bfloat16 g_xs_lo[(size_t)B_ * T_ * N_];
__device__ __align__(16) __nv_bfloat16 g_wkT_hi[(size_t)FM_ * N_];
__device__ __align__(16) __nv_bfloat16 g_wkT_lo[(size_t)FM_ * N_];
__device__ __align__(16) __nv_bfloat16 g_weT_hi[(size_t)T_ * 2 * M_];
__device__ __align__(16) __nv_bfloat16 g_weT_lo[(size_t)T_ * 2 * M_];
__device__ __align__(16) __nv_bfloat16 g_hs_hi[(size_t)T_ * B_ * 2 * M_];
__device__ __align__(16) __nv_bfloat16 g_hs_lo[(size_t)T_ * B_ * 2 * M_];

__device__ __forceinline__ float sigm(float x) {
    return __fdividef(1.0f, 1.0f + __expf(-x));
}
__device__ __forceinline__ float tanh_e(float x) {
    float a = fabsf(x);
    float e = __expf(-2.0f * a);
    float r = __fdividef(1.0f - e, 1.0f + e);
    return copysignf(r, x);
}
__device__ __forceinline__ float tanh_fast(float x) {
    float y;
    asm("tanh.approx.f32 %0, %1;" : "=f"(y) : "f"(x));
    return y;
}
__device__ __forceinline__ unsigned long long fma2(unsigned long long a,
                                                   unsigned long long b,
                                                   unsigned long long c) {
    unsigned long long d;
    asm("fma.rn.f32x2 %0, %1, %2, %3;" : "=l"(d) : "l"(a), "l"(b), "l"(c));
    return d;
}
__device__ __forceinline__ unsigned long long add2(unsigned long long a,
                                                   unsigned long long b) {
    unsigned long long d;
    asm("add.rn.f32x2 %0, %1, %2;" : "=l"(d) : "l"(a), "l"(b));
    return d;
}
__device__ __forceinline__ unsigned long long dup2(float x) {
    unsigned long long r;
    asm("mov.b64 %0, {%1, %1};" : "=l"(r) : "f"(x));
    return r;
}
__device__ __forceinline__ void unpack2(unsigned long long p, float& lo, float& hi) {
    asm("mov.b64 {%0, %1}, %2;" : "=f"(lo), "=f"(hi) : "l"(p));
}
__device__ __forceinline__ void bsplit(float x, __nv_bfloat16& hi, __nv_bfloat16& lo) {
    hi = __float2bfloat16(x);
    lo = __float2bfloat16(x - __bfloat162float(hi));
}

// HMMA m16n8k16 bf16, fp32 accum (sm_80+ PTX, legal on base sm_103 target)
#define MMA16816(c, a, b) \
    asm volatile("mma.sync.aligned.m16n8k16.row.col.f32.bf16.bf16.f32 " \
        "{%0,%1,%2,%3}, {%4,%5,%6,%7}, {%8,%9}, {%0,%1,%2,%3};" \
        : "+f"((c)[0]), "+f"((c)[1]), "+f"((c)[2]), "+f"((c)[3]) \
        : "r"((a)[0]), "r"((a)[1]), "r"((a)[2]), "r"((a)[3]), \
          "r"((b)[0]), "r"((b)[1]))

// ---- init ----
__global__ void k_init(const float* __restrict__ s, const float* __restrict__ h,
                       const float* __restrict__ Wr) {
    int i = blockIdx.x * blockDim.x + threadIdx.x;
    if (i < B_ * M_) {
        g_H[i] = h[i];
        g_S[i] = s[i];
        int b = i >> 8, m = i & 255;
        g_Ht[((size_t)(b >> 5) * 256 + m) * 32 + (b & 31)] = h[i];
    }
    if (i < M_ * FM_) {
        int k = i >> 10, c = i & 1023;
        g_Wrt[((size_t)(k * 256 + (c & 255))) * 4 + (c >> 8)] = Wr[i];
    }
    if (i < 16) g_arr[i] = 0ull;
}

// ---- split x / WkT / WeT into bf16 hi+lo ----
__global__ void k_split(const float* __restrict__ x, const float* __restrict__ Wk,
                        const float* __restrict__ We) {
    size_t i = (size_t)blockIdx.x * blockDim.x + threadIdx.x;
    if (i < (size_t)B_ * T_ * N_) {
        __nv_bfloat16 hi, lo;
        bsplit(x[i], hi, lo);
        g_xs_hi[i] = hi;
        g_xs_lo[i] = lo;
    }
    if (i < (size_t)N_ * FM_) {
        int k = (int)(i >> 10), n = (int)(i & 1023);
        __nv_bfloat16 hi, lo;
        bsplit(Wk[i], hi, lo);
        g_wkT_hi[(size_t)n * 128 + k] = hi;
        g_wkT_lo[(size_t)n * 128 + k] = lo;
    }
    if (i < (size_t)2 * M_ * T_) {
        int k = (int)(i >> 8), u = (int)(i & 255);
        __nv_bfloat16 hi, lo;
        bsplit(We[i], hi, lo);
        g_weT_hi[(size_t)u * 512 + k] = hi;
        g_weT_lo[(size_t)u * 512 + k] = lo;
    }
}

// ---- split [H|S] history into bf16 hi+lo rows [tau*B+b][512] ----
__global__ void k_split_hs() {
    size_t i = (size_t)blockIdx.x * blockDim.x + threadIdx.x;  // 33.5M
    size_t row = i >> 8;
    int m = (int)(i & 255);
    __nv_bfloat16 hi, lo;
    bsplit(g_H[i], hi, lo);
    g_hs_hi[row * 512 + m] = hi;
    g_hs_lo[row * 512 + m] = lo;
    bsplit(g_S[i], hi, lo);
    g_hs_hi[row * 512 + 256 + m] = hi;
    g_hs_lo[row * 512 + 256 + m] = lo;
}

// ---- split-bf16 HMMA GEMM: C[128x128/block] = A @ B^T over nkb K-chunks ----
// smem stride 136 elem: rows 16B-aligned, frag LDS bank-free (4r+tg unique mod 32).
// mode 1: Xk remap + bias; mode 0: R1 direct.
#define SSTR 136
__global__ __launch_bounds__(256, 1)
void k_gemm(const __nv_bfloat16* __restrict__ Ah, const __nv_bfloat16* __restrict__ Al,
            const __nv_bfloat16* __restrict__ Bh, const __nv_bfloat16* __restrict__ Bl,
            int lda, int nkb, const float* __restrict__ bias, float* __restrict__ Cout,
            int mode) {
    extern __shared__ __nv_bfloat16 smg[];
    __nv_bfloat16* ash = smg;
    __nv_bfloat16* asl = ash + 128 * SSTR;
    __nv_bfloat16* bsh = asl + 128 * SSTR;
    __nv_bfloat16* bsl = bsh + 128 * SSTR;
    int tid = threadIdx.x, l = tid & 31, w = tid >> 5;
    int wm = w & 3, wn = w >> 2;       // warp C tile: rows wm*32..+31, cols wn*64..+63
    int rb = blockIdx.x, nb = blockIdx.y;
    int gr = l >> 2, tg = l & 3;

    float acc[2][8][4];
#pragma unroll
    for (int mt = 0; mt < 2; mt++)
#pragma unroll
        for (int nt = 0; nt < 8; nt++)
#pragma unroll
            for (int j = 0; j < 4; j++) acc[mt][nt][j] = 0.f;

    for (int kb = 0; kb < nkb; kb++) {
#pragma unroll
        for (int i = 0; i < 8; i++) {
            int idx = i * 256 + tid;
            int r = idx >> 4, c = (idx & 15) * 8;
            *(uint4*)&ash[r * SSTR + c] =
                *(const uint4*)&Ah[(size_t)(rb * 128 + r) * lda + kb * 128 + c];
            *(uint4*)&asl[r * SSTR + c] =
                *(const uint4*)&Al[(size_t)(rb * 128 + r) * lda + kb * 128 + c];
            *(uint4*)&bsh[r * SSTR + c] =
                *(const uint4*)&Bh[(size_t)(nb * 128 + r) * lda + kb * 128 + c];
            *(uint4*)&bsl[r * SSTR + c] =
                *(const uint4*)&Bl[(size_t)(nb * 128 + r) * lda + kb * 128 + c];
        }
        __syncthreads();
#pragma unroll
        for (int ks = 0; ks < 8; ks++) {
            int k0 = ks * 16;
            uint32_t ah[2][4], al[2][4], bh[8][2], bl[8][2];
#pragma unroll
            for (int mt = 0; mt < 2; mt++) {
                int r = wm * 32 + mt * 16 + gr;
                int c = k0 + tg * 2;
                ah[mt][0] = *(uint32_t*)&ash[r * SSTR + c];
                ah[mt][1] = *(uint32_t*)&ash[(r + 8) * SSTR + c];
                ah[mt][2] = *(uint32_t*)&ash[r * SSTR + c + 8];
                ah[mt][3] = *(uint32_t*)&ash[(r + 8) * SSTR + c + 8];
                al[mt][0] = *(uint32_t*)&asl[r * SSTR + c];
                al[mt][1] = *(uint32_t*)&asl[(r + 8) * SSTR + c];
                al[mt][2] = *(uint32_t*)&asl[r * SSTR + c + 8];
                al[mt][3] = *(uint32_t*)&asl[(r + 8) * SSTR + c + 8];
            }
#pragma unroll
            for (int nt = 0; nt < 8; nt++) {
                int n = wn * 64 + nt * 8 + gr;
                int kk = k0 + tg * 2;
                bh[nt][0] = *(uint32_t*)&bsh[n * SSTR + kk];
                bh[nt][1] = *(uint32_t*)&bsh[n * SSTR + kk + 8];
                bl[nt][0] = *(uint32_t*)&bsl[n * SSTR + kk];
                bl[nt][1] = *(uint32_t*)&bsl[n * SSTR + kk + 8];
            }
#pragma unroll
            for (int mt = 0; mt < 2; mt++)
#pragma unroll
                for (int nt = 0; nt < 8; nt++) {
                    MMA16816(acc[mt][nt], ah[mt], bh[nt]);
                    MMA16816(acc[mt][nt], ah[mt], bl[nt]);
                    MMA16816(acc[mt][nt], al[mt], bh[nt]);
                }
        }
        __syncthreads();
    }

    // store: c0,c1 = (row, col..col+1); c2,c3 = (row+8, col..col+1)
#pragma unroll
    for (int mt = 0; mt < 2; mt++)
#pragma unroll
        for (int nt = 0; nt < 8; nt++) {
            int row = rb * 128 + wm * 32 + mt * 16 + gr;
            int col = nb * 128 + wn * 64 + nt * 8 + tg * 2;
#pragma unroll
            for (int hf = 0; hf < 2; hf++) {
                int rr = row + hf * 8;
                float v0 = acc[mt][nt][hf * 2 + 0];
                float v1 = acc[mt][nt][hf * 2 + 1];
                if (mode == 1) {
                    v0 += bias[col];
                    v1 += bias[col + 1];
                    int t = rr & 255, b = rr >> 8;
                    *(float2*)&Cout[((size_t)t * 512 + b) * 1024 + col] =
                        make_float2(v0, v1);
                } else {
                    *(float2*)&Cout[(size_t)rr * 256 + col] = make_float2(v0, v1);
                }
            }
        }
}

// ---- r2 (unchanged) ----
__global__ __launch_bounds__(256) void k_r2(const float* __restrict__ x,
                                            const float* __restrict__ Ue) {
    int b = blockIdx.x;
    int ut = blockIdx.y * 64;
    __shared__ float xs[32][128];
    __shared__ float us[32][64];
    int tid = threadIdx.x;
    int n0 = (tid & 31) * 4;
    int u0 = (tid >> 5) * 8;
    float acc[8][4];
#pragma unroll
    for (int j = 0; j < 8; j++)
#pragma unroll
        for (int i = 0; i < 4; i++) acc[j][i] = 0.f;
    for (int kt = 0; kt < T_; kt += 32) {
#pragma unroll
        for (int l = 0; l < 4; l++) {
            int idx = l * 256 + tid;
            int t = idx >> 5, n4 = idx & 31;
            *(float4*)&xs[t][n4 * 4] =
                ((const float4*)x)[(size_t)(b * T_ + kt + t) * 32 + n4];
        }
#pragma unroll
        for (int l = 0; l < 2; l++) {
            int idx = l * 256 + tid;
            int t = idx >> 4, u4 = idx & 15;
            *(float4*)&us[t][u4 * 4] =
                ((const float4*)Ue)[(size_t)(kt + t) * 64 + (ut >> 2) + u4];
        }
        __syncthreads();
#pragma unroll 8
        for (int k = 0; k < 32; k++) {
            float4 x4 = *(const float4*)&xs[k][n0];
            float4 ua = *(const float4*)&us[k][u0];
            float4 ub = *(const float4*)&us[k][u0 + 4];
            float xv[4] = {x4.x, x4.y, x4.z, x4.w};
            float uu[8] = {ua.x, ua.y, ua.z, ua.w, ub.x, ub.y, ub.z, ub.w};
#pragma unroll
            for (int j = 0; j < 8; j++)
#pragma unroll
                for (int i = 0; i < 4; i++) acc[j][i] += xv[i] * uu[j];
        }
        __syncthreads();
    }
#pragma unroll
    for (int i = 0; i < 4; i++) {
        size_t base = ((size_t)(b * N_ + n0 + i)) * T_ + ut + u0;
        *(float4*)&g_r2[base] = make_float4(acc[0][i], acc[1][i], acc[2][i], acc[3][i]);
        *(float4*)&g_r2[base + 4] = make_float4(acc[4][i], acc[5][i], acc[6][i], acc[7][i]);
    }
}

// ---- persistent LSTM (R9 best variant, unchanged) ----
__global__ __launch_bounds__(512, 1) void k_lstm_all() {
    extern __shared__ char smc[];
    float* ws = (float*)smc;
    float* hs = (float*)(smc + 131072);
    unsigned long long* pp = (unsigned long long*)(smc + 131072);
    const ulonglong2* wsv = (const ulonglong2*)ws;
    const float4* hsv = (const float4*)hs;

    int tid = threadIdx.x;
    int bx = blockIdx.x >> 3;
    int by = blockIdx.x & 7;
    int ml = tid & 31;
    int mg = by * 32 + ml;
    int rt = (tid >> 5) & 7;
    int kh = tid >> 8;
    int k0 = kh * 128;

#pragma unroll
    for (int l = 0; l < 16; l++) {
        int f = l * 512 + tid;
        int k = f >> 5, mm = f & 31;
        ((float4*)ws)[f] = ((const float4*)g_Wrt)[(size_t)k * 256 + by * 32 + mm];
    }
    float s4[4];
    float px[4][4];
    if (kh == 0) {
#pragma unroll
        for (int i = 0; i < 4; i++) {
            int b = bx * 32 + rt * 4 + i;
            s4[i] = g_S[(size_t)b * M_ + mg];
            size_t xo = (size_t)b * FM_ + mg;
            px[i][0] = g_Xk[xo];
            px[i][1] = g_Xk[xo + 256];
            px[i][2] = g_Xk[xo + 512];
            px[i][3] = g_Xk[xo + 768];
        }
    }
#pragma unroll
    for (int l = 0; l < 4; l++) {
        int idx = l * 512 + tid;
        ((float4*)hs)[idx] = ((const float4*)g_Ht)[(size_t)bx * 2048 + idx];
    }
    __syncthreads();

    for (int t = 0; t < T_; t++) {
        unsigned long long aif[4], ago[4];
#pragma unroll
        for (int i = 0; i < 4; i++) { aif[i] = 0ull; ago[i] = 0ull; }
#pragma unroll 8
        for (int kk = 0; kk < 128; kk++) {
            int k = k0 + kk;
            ulonglong2 wv = wsv[k * 32 + ml];
            float4 h4 = hsv[k * 8 + rt];
            unsigned long long d0 = dup2(h4.x);
            unsigned long long d1 = dup2(h4.y);
            unsigned long long d2 = dup2(h4.z);
            unsigned long long d3 = dup2(h4.w);
            aif[0] = fma2(d0, wv.x, aif[0]);  ago[0] = fma2(d0, wv.y, ago[0]);
            aif[1] = fma2(d1, wv.x, aif[1]);  ago[1] = fma2(d1, wv.y, ago[1]);
            aif[2] = fma2(d2, wv.x, aif[2]);  ago[2] = fma2(d2, wv.y, ago[2]);
            aif[3] = fma2(d3, wv.x, aif[3]);  ago[3] = fma2(d3, wv.y, ago[3]);
        }
        __syncthreads();
        if (kh == 1) {
            int o = (tid - 256) * 8;
            pp[o + 0] = aif[0]; pp[o + 1] = aif[1];
            pp[o + 2] = aif[2]; pp[o + 3] = aif[3];
            pp[o + 4] = ago[0]; pp[o + 5] = ago[1];
            pp[o + 6] = ago[2]; pp[o + 7] = ago[3];
        }
        __syncthreads();
        if (kh == 0) {
            int o = tid * 8;
            float hv[4];
#pragma unroll
            for (int i = 0; i < 4; i++) {
                unsigned long long zif = add2(aif[i], pp[o + i]);
                unsigned long long zgo = add2(ago[i], pp[o + 4 + i]);
                int b = bx * 32 + rt * 4 + i;
                float zi, zf, zg, zo;
                unpack2(zif, zi, zf);
                unpack2(zgo, zg, zo);
                zi += px[i][0];
                zf += px[i][1];
                zg += px[i][2];
                zo += px[i][3];
                float ig = sigm(zi), fg = sigm(zf), og = sigm(zo);
                float gg = tanh_e(zg);
                float sn = fg * s4[i] + ig * gg;
                float hn = og * tanh_e(sn);
                s4[i] = sn;
                hv[i] = hn;
                size_t dn = ((size_t)(t + 1) * B_ + b) * M_ + mg;
                g_S[dn] = sn;
                g_H[dn] = hn;
            }
            ((float4*)g_Ht)[(((size_t)(t + 1) * 16 + bx) * 256 + mg) * 8 + rt] =
                make_float4(hv[0], hv[1], hv[2], hv[3]);
            int tn = (t < T_ - 1) ? t + 1 : t;
#pragma unroll
            for (int i = 0; i < 4; i++) {
                int b = bx * 32 + rt * 4 + i;
                size_t xo = ((size_t)tn * B_ + b) * FM_ + mg;
                px[i][0] = g_Xk[xo];
                px[i][1] = g_Xk[xo + 256];
                px[i][2] = g_Xk[xo + 512];
                px[i][3] = g_Xk[xo + 768];
            }
        }
        __syncthreads();
        if (tid == 0) {
            __threadfence();
            atomicAdd(&g_arr[bx], 1ull);
        }
        unsigned long long tgt = 8ull * (unsigned long long)(t + 1);
        while (*((volatile unsigned long long*)&g_arr[bx]) < tgt) {}
#pragma unroll
        for (int l = 0; l < 4; l++) {
            int idx = l * 512 + tid;
            ((float4*)hs)[idx] =
                ((const float4*)g_Ht)[((size_t)(t + 1) * 16 + bx) * 2048 + idx];
        }
        __syncthreads();
    }
}

// ---- fused e/softmax/output (unchanged) ----
__global__ __launch_bounds__(512) void k_e(const float* __restrict__ x,
                                           const float* __restrict__ ve,
                                           float* __restrict__ out) {
    extern __shared__ float r2s[];
    __shared__ float r1s[4][256];
    __shared__ float ves[256];
    __shared__ float redm[16];
    __shared__ float reds[16];
    int b = blockIdx.x;
    int tau0 = blockIdx.y * 32;
    int tid = threadIdx.x;
    int lane = tid & 31;
    int warp = tid >> 5;
    int q = tid >> 7;
    int n = tid & 127;

    if (tid < 256) ves[tid] = ve[tid];
#pragma unroll
    for (int l = 0; l < 16; l++) {
        int idx = l * 512 + tid;
        int nn = idx >> 6, u4 = idx & 63;
        float4 v = ((const float4*)g_r2)[(size_t)(b * N_ + nn) * 64 + u4];
        *(float4*)&r2s[nn * 260 + u4 * 4] = v;
    }
    __syncthreads();
    const float* rp = &r2s[n * 260];

    for (int ti = 0; ti < 8; ti++) {
#pragma unroll
        for (int l = 0; l < 2; l++) {
            int idx = l * 512 + tid;
            int wh = idx >> 8, u = idx & 255;
            r1s[wh][u] = g_R1[((size_t)(tau0 + ti * 4 + wh) * B_ + b) * T_ + u];
        }
        __syncthreads();
        const float* r1p = r1s[q];
        float acc0 = 0.f, acc1 = 0.f;
#pragma unroll 4
        for (int u4 = 0; u4 < 64; u4++) {
            float4 rv = *(const float4*)&rp[u4 * 4];
            float4 r1 = *(const float4*)&r1p[u4 * 4];
            float4 vv = *(const float4*)&ves[u4 * 4];
            acc0 += tanh_fast(r1.x + rv.x) * vv.x;
            acc1 += tanh_fast(r1.y + rv.y) * vv.y;
            acc0 += tanh_fast(r1.z + rv.z) * vv.z;
            acc1 += tanh_fast(r1.w + rv.w) * vv.w;
        }
        float e = acc0 + acc1;
        float mx = e;
#pragma unroll
        for (int off = 16; off >= 1; off >>= 1)
            mx = fmaxf(mx, __shfl_xor_sync(0xffffffffu, mx, off));
        if (lane == 0) redm[warp] = mx;
        __syncthreads();
        mx = fmaxf(fmaxf(redm[q * 4], redm[q * 4 + 1]),
                   fmaxf(redm[q * 4 + 2], redm[q * 4 + 3]));
        float ex = __expf(e - mx);
        float sm = ex;
#pragma unroll
        for (int off = 16; off >= 1; off >>= 1)
            sm += __shfl_xor_sync(0xffffffffu, sm, off);
        if (lane == 0) reds[warp] = sm;
        __syncthreads();
        sm = reds[q * 4] + reds[q * 4 + 1] + reds[q * 4 + 2] + reds[q * 4 + 3];
        float alpha = ex / sm;
        int tau = tau0 + ti * 4 + q;
        size_t oi = ((size_t)b * T_ + tau) * N_ + n;
        out[oi] = alpha * x[oi];
        __syncthreads();
    }
}

extern "C" void kernel_launch(void* const* d_in, const int* in_sizes, int n_in,
                              void* d_out, int out_size) {
    const float* x  = (const float*)d_in[0];
    const float* s  = (const float*)d_in[1];
    const float* h  = (const float*)d_in[2];
    const float* We = (const float*)d_in[3];
    const float* Ue = (const float*)d_in[4];
    const float* ve = (const float*)d_in[5];
    const float* Wk = (const float*)d_in[6];
    const float* Wr = (const float*)d_in[7];
    const float* bb = (const float*)d_in[8];
    float* out = (float*)d_out;
    (void)in_sizes; (void)n_in; (void)out_size;

    float *xk_p, *r1_p;
    cudaGetSymbolAddress((void**)&xk_p, g_Xk);
    cudaGetSymbolAddress((void**)&r1_p, g_R1);
    __nv_bfloat16 *xs_hi, *xs_lo, *wk_hi, *wk_lo, *we_hi, *we_lo, *hs_hi, *hs_lo;
    cudaGetSymbolAddress((void**)&xs_hi, g_xs_hi);
    cudaGetSymbolAddress((void**)&xs_lo, g_xs_lo);
    cudaGetSymbolAddress((void**)&wk_hi, g_wkT_hi);
    cudaGetSymbolAddress((void**)&wk_lo, g_wkT_lo);
    cudaGetSymbolAddress((void**)&we_hi, g_weT_hi);
    cudaGetSymbolAddress((void**)&we_lo, g_weT_lo);
    cudaGetSymbolAddress((void**)&hs_hi, g_hs_hi);
    cudaGetSymbolAddress((void**)&hs_lo, g_hs_lo);

    k_init<<<1024, 256>>>(s, h, Wr);
    k_split<<<65536, 256>>>(x, Wk, We);
    k_r2<<<dim3(B_, 4), 256>>>(x, Ue);

    const int SMG = 4 * 128 * SSTR * 2;  // 139264 B
    cudaFuncSetAttribute(k_gemm, cudaFuncAttributeMaxDynamicSharedMemorySize, SMG);
    k_gemm<<<dim3(1024, 8), 256, SMG>>>(xs_hi, xs_lo, wk_hi, wk_lo, 128, 1, bb, xk_p, 1);

    const int SML = 131072 + 32768;
    cudaFuncSetAttribute(k_lstm_all, cudaFuncAttributeMaxDynamicSharedMemorySize, SML);
    k_lstm_all<<<GRID_LSTM, 512, SML>>>();

    k_split_hs<<<131072, 256>>>();
    k_gemm<<<dim3(1024, 2), 256, SMG>>>(hs_hi, hs_lo, we_hi, we_lo, 512, 4,
                                        (const float*)nullptr, r1_p, 0);

    const int SME = 128 * 260 * (int)sizeof(float);
    cudaFuncSetAttribute(k_e, cudaFuncAttributeMaxDynamicSharedMemorySize, SME);
    k_e<<<dim3(B_, 8), 512, SME>>>(x, ve, out);
}

// round 14
// speedup vs baseline: 1.5897x; 1.2598x over previous
#include <cuda_runtime.h>
#include <cuda_bf16.h>
#include <math.h>
#include <stdint.h>

#define B_ 512
#define T_ 256
#define N_ 128
#define M_ 256
#define FM_ 1024
#define GRID_LSTM 128

__device__ float g_r2[(size_t)B_ * N_ * T_];
__device__ float g_Xk[(size_t)T_ * B_ * FM_];
__device__ float g_H[(size_t)(T_ + 1) * B_ * M_];
__device__ float g_R1[(size_t)T_ * B_ * T_];
__device__ unsigned long long g_arr[16];

__device__ __align__(16) __nv_bfloat16 g_xs_hi[(size_t)B_ * T_ * N_];
__device__ __align__(16) __nv_bfloat16 g_xs_lo[(size_t)B_ * T_ * N_];
__device__ __align__(16) __nv_bfloat16 g_wkT_hi[(size_t)FM_ * N_];
__device__ __align__(16) __nv_bfloat16 g_wkT_lo[(size_t)FM_ * N_];
__device__ __align__(16) __nv_bfloat16 g_weT_hi[(size_t)T_ * 2 * M_];
__device__ __align__(16) __nv_bfloat16 g_weT_lo[(size_t)T_ * 2 * M_];
__device__ __align__(16) __nv_bfloat16 g_hs_hi[(size_t)T_ * B_ * 2 * M_];
__device__ __align__(16) __nv_bfloat16 g_hs_lo[(size_t)T_ * B_ * 2 * M_];
__device__ __align__(16) __nv_bfloat16 g_wrT_hi[(size_t)FM_ * M_];
__device__ __align__(16) __nv_bfloat16 g_wrT_lo[(size_t)FM_ * M_];

__device__ __forceinline__ float sigm(float x) {
    return __fdividef(1.0f, 1.0f + __expf(-x));
}
__device__ __forceinline__ float tanh_e(float x) {
    float a = fabsf(x);
    float e = __expf(-2.0f * a);
    float r = __fdividef(1.0f - e, 1.0f + e);
    return copysignf(r, x);
}
__device__ __forceinline__ float tanh_fast(float x) {
    float y;
    asm("tanh.approx.f32 %0, %1;" : "=f"(y) : "f"(x));
    return y;
}
__device__ __forceinline__ void bsplit(float x, __nv_bfloat16& hi, __nv_bfloat16& lo) {
    hi = __float2bfloat16(x);
    lo = __float2bfloat16(x - __bfloat162float(hi));
}
__device__ __forceinline__ uint32_t pk2(__nv_bfloat16 a, __nv_bfloat16 b) {
    unsigned short xa = *(unsigned short*)&a, xb = *(unsigned short*)&b;
    return (uint32_t)xa | ((uint32_t)xb << 16);
}

#define MMA16816(c, a, b) \
    asm volatile("mma.sync.aligned.m16n8k16.row.col.f32.bf16.bf16.f32 " \
        "{%0,%1,%2,%3}, {%4,%5,%6,%7}, {%8,%9}, {%0,%1,%2,%3};" \
        : "+f"((c)[0]), "+f"((c)[1]), "+f"((c)[2]), "+f"((c)[3]) \
        : "r"((a)[0]), "r"((a)[1]), "r"((a)[2]), "r"((a)[3]), \
          "r"((b)[0]), "r"((b)[1]))

// ---- init: H slot0 + hs slot0, reset barriers ----
__global__ void k_init(const float* __restrict__ s, const float* __restrict__ h) {
    int i = blockIdx.x * blockDim.x + threadIdx.x;
    if (i < B_ * M_) {
        g_H[i] = h[i];
        int b = i >> 8, m = i & 255;
        __nv_bfloat16 hi, lo;
        bsplit(h[i], hi, lo);
        g_hs_hi[(size_t)b * 512 + m] = hi;
        g_hs_lo[(size_t)b * 512 + m] = lo;
        bsplit(s[i], hi, lo);
        g_hs_hi[(size_t)b * 512 + 256 + m] = hi;
        g_hs_lo[(size_t)b * 512 + 256 + m] = lo;
    }
    if (i < 16) g_arr[i] = 0ull;
}

// ---- split x / WkT / WeT / WrT(gate-interleaved) into bf16 hi+lo ----
__global__ void k_split(const float* __restrict__ x, const float* __restrict__ Wk,
                        const float* __restrict__ We, const float* __restrict__ Wr) {
    size_t i = (size_t)blockIdx.x * blockDim.x + threadIdx.x;
    __nv_bfloat16 hi, lo;
    if (i < (size_t)B_ * T_ * N_) {
        bsplit(x[i], hi, lo);
        g_xs_hi[i] = hi;
        g_xs_lo[i] = lo;
    }
    if (i < (size_t)N_ * FM_) {
        int k = (int)(i >> 10), n = (int)(i & 1023);
        bsplit(Wk[i], hi, lo);
        g_wkT_hi[(size_t)n * 128 + k] = hi;
        g_wkT_lo[(size_t)n * 128 + k] = lo;
    }
    if (i < (size_t)2 * M_ * T_) {
        int k = (int)(i >> 8), u = (int)(i & 255);
        bsplit(We[i], hi, lo);
        g_weT_hi[(size_t)u * 512 + k] = hi;
        g_weT_lo[(size_t)u * 512 + k] = lo;
    }
    if (i < (size_t)M_ * FM_) {   // Wr [256 k][1024 c] -> [by*128+ml*4+g][k]
        int k = (int)(i >> 10), c = (int)(i & 1023);
        int g = c >> 8, m = c & 255;
        int col2 = (m >> 5) * 128 + (m & 31) * 4 + g;
        bsplit(Wr[i], hi, lo);
        g_wrT_hi[(size_t)col2 * 256 + k] = hi;
        g_wrT_lo[(size_t)col2 * 256 + k] = lo;
    }
}

// ---- split-bf16 HMMA GEMM (R13, validated): C = A @ B^T ----
#define SSTR 136
__global__ __launch_bounds__(256, 1)
void k_gemm(const __nv_bfloat16* __restrict__ Ah, const __nv_bfloat16* __restrict__ Al,
            const __nv_bfloat16* __restrict__ Bh, const __nv_bfloat16* __restrict__ Bl,
            int lda, int nkb, const float* __restrict__ bias, float* __restrict__ Cout,
            int mode) {
    extern __shared__ __nv_bfloat16 smg[];
    __nv_bfloat16* ash = smg;
    __nv_bfloat16* asl = ash + 128 * SSTR;
    __nv_bfloat16* bsh = asl + 128 * SSTR;
    __nv_bfloat16* bsl = bsh + 128 * SSTR;
    int tid = threadIdx.x, l = tid & 31, w = tid >> 5;
    int wm = w & 3, wn = w >> 2;
    int rb = blockIdx.x, nb = blockIdx.y;
    int gr = l >> 2, tg = l & 3;

    float acc[2][8][4];
#pragma unroll
    for (int mt = 0; mt < 2; mt++)
#pragma unroll
        for (int nt = 0; nt < 8; nt++)
#pragma unroll
            for (int j = 0; j < 4; j++) acc[mt][nt][j] = 0.f;

    for (int kb = 0; kb < nkb; kb++) {
#pragma unroll
        for (int i = 0; i < 8; i++) {
            int idx = i * 256 + tid;
            int r = idx >> 4, c = (idx & 15) * 8;
            *(uint4*)&ash[r * SSTR + c] =
                *(const uint4*)&Ah[(size_t)(rb * 128 + r) * lda + kb * 128 + c];
            *(uint4*)&asl[r * SSTR + c] =
                *(const uint4*)&Al[(size_t)(rb * 128 + r) * lda + kb * 128 + c];
            *(uint4*)&bsh[r * SSTR + c] =
                *(const uint4*)&Bh[(size_t)(nb * 128 + r) * lda + kb * 128 + c];
            *(uint4*)&bsl[r * SSTR + c] =
                *(const uint4*)&Bl[(size_t)(nb * 128 + r) * lda + kb * 128 + c];
        }
        __syncthreads();
#pragma unroll
        for (int ks = 0; ks < 8; ks++) {
            int k0 = ks * 16;
            uint32_t ah[2][4], al[2][4], bh[8][2], bl[8][2];
#pragma unroll
            for (int mt = 0; mt < 2; mt++) {
                int r = wm * 32 + mt * 16 + gr;
                int c = k0 + tg * 2;
                ah[mt][0] = *(uint32_t*)&ash[r * SSTR + c];
                ah[mt][1] = *(uint32_t*)&ash[(r + 8) * SSTR + c];
                ah[mt][2] = *(uint32_t*)&ash[r * SSTR + c + 8];
                ah[mt][3] = *(uint32_t*)&ash[(r + 8) * SSTR + c + 8];
                al[mt][0] = *(uint32_t*)&asl[r * SSTR + c];
                al[mt][1] = *(uint32_t*)&asl[(r + 8) * SSTR + c];
                al[mt][2] = *(uint32_t*)&asl[r * SSTR + c + 8];
                al[mt][3] = *(uint32_t*)&asl[(r + 8) * SSTR + c + 8];
            }
#pragma unroll
            for (int nt = 0; nt < 8; nt++) {
                int n = wn * 64 + nt * 8 + gr;
                int kk = k0 + tg * 2;
                bh[nt][0] = *(uint32_t*)&bsh[n * SSTR + kk];
                bh[nt][1] = *(uint32_t*)&bsh[n * SSTR + kk + 8];
                bl[nt][0] = *(uint32_t*)&bsl[n * SSTR + kk];
                bl[nt][1] = *(uint32_t*)&bsl[n * SSTR + kk + 8];
            }
#pragma unroll
            for (int mt = 0; mt < 2; mt++)
#pragma unroll
                for (int nt = 0; nt < 8; nt++) {
                    MMA16816(acc[mt][nt], ah[mt], bh[nt]);
                    MMA16816(acc[mt][nt], ah[mt], bl[nt]);
                    MMA16816(acc[mt][nt], al[mt], bh[nt]);
                }
        }
        __syncthreads();
    }
#pragma unroll
    for (int mt = 0; mt < 2; mt++)
#pragma unroll
        for (int nt = 0; nt < 8; nt++) {
            int row = rb * 128 + wm * 32 + mt * 16 + gr;
            int col = nb * 128 + wn * 64 + nt * 8 + tg * 2;
#pragma unroll
            for (int hf = 0; hf < 2; hf++) {
                int rr = row + hf * 8;
                float v0 = acc[mt][nt][hf * 2 + 0];
                float v1 = acc[mt][nt][hf * 2 + 1];
                if (mode == 1) {
                    v0 += bias[col];
                    v1 += bias[col + 1];
                    int t = rr & 255, b = rr >> 8;
                    *(float2*)&Cout[((size_t)t * 512 + b) * 1024 + col] =
                        make_float2(v0, v1);
                } else {
                    *(float2*)&Cout[(size_t)rr * 256 + col] = make_float2(v0, v1);
                }
            }
        }
}

// ---- persistent LSTM with HMMA GEMM ----
// grid 128 = 16 bx x 8 by; block 256 (8 warps: wm 0..1 x wn 0..3).
// C[32 rows][128 cols=gate-interleaved] = H[32x256] @ WrT_slice[128x256]^T, 3 passes.
#define WSTR 264   // bf16 elems/row (528B: 16B-aligned, banks 4*gr+tg conflict-free)
#define CSTR 132   // fp32/row
__global__ __launch_bounds__(256, 1) void k_lstm_mma(const float* __restrict__ s_in) {
    extern __shared__ char smc[];
    __nv_bfloat16* wbh = (__nv_bfloat16*)smc;             // [128][WSTR]
    __nv_bfloat16* wbl = wbh + 128 * WSTR;
    __nv_bfloat16* ahh = wbl + 128 * WSTR;                // [32][WSTR]
    __nv_bfloat16* ahl = ahh + 32 * WSTR;
    float* cs = (float*)(ahl + 32 * WSTR);                // [32][CSTR]

    int tid = threadIdx.x, l = tid & 31, w = tid >> 5;
    int bx = blockIdx.x >> 3, by = blockIdx.x & 7;
    int wm = w & 1, wn = w >> 1;
    int gr = l >> 2, tg = l & 3;
    int ml = tid & 31, rg = tid >> 5;     // epilogue: m=ml, rows rg*4..+3
    int mg = by * 32 + ml;

    // stage weights once: [col2 local 0..127][k 0..255]
#pragma unroll
    for (int i = 0; i < 16; i++) {
        int idx = i * 256 + tid;
        int c = idx >> 5, kc = (idx & 31) * 8;
        *(uint4*)&wbh[c * WSTR + kc] =
            *(const uint4*)&g_wrT_hi[(size_t)(by * 128 + c) * 256 + kc];
        *(uint4*)&wbl[c * WSTR + kc] =
            *(const uint4*)&g_wrT_lo[(size_t)(by * 128 + c) * 256 + kc];
    }

    float s4[4], px[4][4];
#pragma unroll
    for (int i = 0; i < 4; i++) {
        int b = bx * 32 + rg * 4 + i;
        s4[i] = s_in[(size_t)b * 256 + mg];
        size_t xo = (size_t)b * FM_ + mg;
        px[i][0] = g_Xk[xo];
        px[i][1] = g_Xk[xo + 256];
        px[i][2] = g_Xk[xo + 512];
        px[i][3] = g_Xk[xo + 768];
    }
    __syncthreads();

    int sr = tid >> 3, sm0 = (tid & 7) * 32;   // A staging: row sr, 32 m
    for (int t = 0; t < T_; t++) {
        // stage A: split H[t] rows into bf16 hi/lo smem
#pragma unroll
        for (int j = 0; j < 8; j++) {
            float4 v = *(const float4*)&g_H[((size_t)t * 512 + bx * 32 + sr) * 256 +
                                            sm0 + j * 4];
            __nv_bfloat16 h0, h1, h2, h3, q0, q1, q2, q3;
            bsplit(v.x, h0, q0);
            bsplit(v.y, h1, q1);
            bsplit(v.z, h2, q2);
            bsplit(v.w, h3, q3);
            *(uint2*)&ahh[sr * WSTR + sm0 + j * 4] = make_uint2(pk2(h0, h1), pk2(h2, h3));
            *(uint2*)&ahl[sr * WSTR + sm0 + j * 4] = make_uint2(pk2(q0, q1), pk2(q2, q3));
        }
        __syncthreads();

        // GEMM: acc[4 ntiles][4]
        float acc[4][4];
#pragma unroll
        for (int nt = 0; nt < 4; nt++)
#pragma unroll
            for (int j = 0; j < 4; j++) acc[nt][j] = 0.f;
#pragma unroll
        for (int ks = 0; ks < 16; ks++) {
            int k0 = ks * 16;
            int ar = wm * 16 + gr;
            int c = k0 + tg * 2;
            uint32_t ah[4], al[4];
            ah[0] = *(uint32_t*)&ahh[ar * WSTR + c];
            ah[1] = *(uint32_t*)&ahh[(ar + 8) * WSTR + c];
            ah[2] = *(uint32_t*)&ahh[ar * WSTR + c + 8];
            ah[3] = *(uint32_t*)&ahh[(ar + 8) * WSTR + c + 8];
            al[0] = *(uint32_t*)&ahl[ar * WSTR + c];
            al[1] = *(uint32_t*)&ahl[(ar + 8) * WSTR + c];
            al[2] = *(uint32_t*)&ahl[ar * WSTR + c + 8];
            al[3] = *(uint32_t*)&ahl[(ar + 8) * WSTR + c + 8];
#pragma unroll
            for (int nt = 0; nt < 4; nt++) {
                int bc = wn * 32 + nt * 8 + gr;
                uint32_t bh[2], bl2[2];
                bh[0] = *(uint32_t*)&wbh[bc * WSTR + c];
                bh[1] = *(uint32_t*)&wbh[bc * WSTR + c + 8];
                bl2[0] = *(uint32_t*)&wbl[bc * WSTR + c];
                bl2[1] = *(uint32_t*)&wbl[bc * WSTR + c + 8];
                MMA16816(acc[nt], ah, bh);
                MMA16816(acc[nt], ah, bl2);
                MMA16816(acc[nt], al, bh);
            }
        }
        // C -> smem
#pragma unroll
        for (int nt = 0; nt < 4; nt++) {
            int row = wm * 16 + gr;
            int col = wn * 32 + nt * 8 + tg * 2;
            *(float2*)&cs[row * CSTR + col] = make_float2(acc[nt][0], acc[nt][1]);
            *(float2*)&cs[(row + 8) * CSTR + col] = make_float2(acc[nt][2], acc[nt][3]);
        }
        __syncthreads();

        // epilogue: 4 rows per thread, all 4 gates via one LDS.128
#pragma unroll
        for (int i = 0; i < 4; i++) {
            int r = rg * 4 + i;
            int b = bx * 32 + r;
            float4 z4 = *(float4*)&cs[r * CSTR + ml * 4];
            float zi = z4.x + px[i][0];
            float zf = z4.y + px[i][1];
            float zg = z4.z + px[i][2];
            float zo = z4.w + px[i][3];
            float ig = sigm(zi), fg = sigm(zf), og = sigm(zo);
            float gg = tanh_e(zg);
            float sn = fg * s4[i] + ig * gg;
            float hn = og * tanh_e(sn);
            s4[i] = sn;
            g_H[((size_t)(t + 1) * 512 + b) * 256 + mg] = hn;
            if (t < 255) {
                size_t ra = ((size_t)(t + 1) * 512 + b) * 512;
                __nv_bfloat16 hi, lo;
                bsplit(hn, hi, lo);
                g_hs_hi[ra + mg] = hi;
                g_hs_lo[ra + mg] = lo;
                bsplit(sn, hi, lo);
                g_hs_hi[ra + 256 + mg] = hi;
                g_hs_lo[ra + 256 + mg] = lo;
            }
        }
        // prefetch next Xk
        int tn = (t < T_ - 1) ? t + 1 : t;
#pragma unroll
        for (int i = 0; i < 4; i++) {
            int b = bx * 32 + rg * 4 + i;
            size_t xo = ((size_t)tn * B_ + b) * FM_ + mg;
            px[i][0] = g_Xk[xo];
            px[i][1] = g_Xk[xo + 256];
            px[i][2] = g_Xk[xo + 512];
            px[i][3] = g_Xk[xo + 768];
        }
        __syncthreads();
        if (tid == 0) {
            __threadfence();
            atomicAdd(&g_arr[bx], 1ull);
        }
        unsigned long long tgt = 8ull * (unsigned long long)(t + 1);
        while (*((volatile unsigned long long*)&g_arr[bx]) < tgt) {}
        __syncthreads();
    }
}

// ---- r2 (unchanged) ----
__global__ __launch_bounds__(256) void k_r2(const float* __restrict__ x,
                                            const float* __restrict__ Ue) {
    int b = blockIdx.x;
    int ut = blockIdx.y * 64;
    __shared__ float xs[32][128];
    __shared__ float us[32][64];
    int tid = threadIdx.x;
    int n0 = (tid & 31) * 4;
    int u0 = (tid >> 5) * 8;
    float acc[8][4];
#pragma unroll
    for (int j = 0; j < 8; j++)
#pragma unroll
        for (int i = 0; i < 4; i++) acc[j][i] = 0.f;
    for (int kt = 0; kt < T_; kt += 32) {
#pragma unroll
        for (int l = 0; l < 4; l++) {
            int idx = l * 256 + tid;
            int t = idx >> 5, n4 = idx & 31;
            *(float4*)&xs[t][n4 * 4] =
                ((const float4*)x)[(size_t)(b * T_ + kt + t) * 32 + n4];
        }
#pragma unroll
        for (int l = 0; l < 2; l++) {
            int idx = l * 256 + tid;
            int t = idx >> 4, u4 = idx & 15;
            *(float4*)&us[t][u4 * 4] =
                ((const float4*)Ue)[(size_t)(kt + t) * 64 + (ut >> 2) + u4];
        }
        __syncthreads();
#pragma unroll 8
        for (int k = 0; k < 32; k++) {
            float4 x4 = *(const float4*)&xs[k][n0];
            float4 ua = *(const float4*)&us[k][u0];
            float4 ub = *(const float4*)&us[k][u0 + 4];
            float xv[4] = {x4.x, x4.y, x4.z, x4.w};
            float uu[8] = {ua.x, ua.y, ua.z, ua.w, ub.x, ub.y, ub.z, ub.w};
#pragma unroll
            for (int j = 0; j < 8; j++)
#pragma unroll
                for (int i = 0; i < 4; i++) acc[j][i] += xv[i] * uu[j];
        }
        __syncthreads();
    }
#pragma unroll
    for (int i = 0; i < 4; i++) {
        size_t base = ((size_t)(b * N_ + n0 + i)) * T_ + ut + u0;
        *(float4*)&g_r2[base] = make_float4(acc[0][i], acc[1][i], acc[2][i], acc[3][i]);
        *(float4*)&g_r2[base + 4] = make_float4(acc[4][i], acc[5][i], acc[6][i], acc[7][i]);
    }
}

// ---- fused e/softmax/output (unchanged) ----
__global__ __launch_bounds__(512) void k_e(const float* __restrict__ x,
                                           const float* __restrict__ ve,
                                           float* __restrict__ out) {
    extern __shared__ float r2s[];
    __shared__ float r1s[4][256];
    __shared__ float ves[256];
    __shared__ float redm[16];
    __shared__ float reds[16];
    int b = blockIdx.x;
    int tau0 = blockIdx.y * 32;
    int tid = threadIdx.x;
    int lane = tid & 31;
    int warp = tid >> 5;
    int q = tid >> 7;
    int n = tid & 127;

    if (tid < 256) ves[tid] = ve[tid];
#pragma unroll
    for (int l = 0; l < 16; l++) {
        int idx = l * 512 + tid;
        int nn = idx >> 6, u4 = idx & 63;
        float4 v = ((const float4*)g_r2)[(size_t)(b * N_ + nn) * 64 + u4];
        *(float4*)&r2s[nn * 260 + u4 * 4] = v;
    }
    __syncthreads();
    const float* rp = &r2s[n * 260];

    for (int ti = 0; ti < 8; ti++) {
#pragma unroll
        for (int l = 0; l < 2; l++) {
            int idx = l * 512 + tid;
            int wh = idx >> 8, u = idx & 255;
            r1s[wh][u] = g_R1[((size_t)(tau0 + ti * 4 + wh) * B_ + b) * T_ + u];
        }
        __syncthreads();
        const float* r1p = r1s[q];
        float acc0 = 0.f, acc1 = 0.f;
#pragma unroll 4
        for (int u4 = 0; u4 < 64; u4++) {
            float4 rv = *(const float4*)&rp[u4 * 4];
            float4 r1 = *(const float4*)&r1p[u4 * 4];
            float4 vv = *(const float4*)&ves[u4 * 4];
            acc0 += tanh_fast(r1.x + rv.x) * vv.x;
            acc1 += tanh_fast(r1.y + rv.y) * vv.y;
            acc0 += tanh_fast(r1.z + rv.z) * vv.z;
            acc1 += tanh_fast(r1.w + rv.w) * vv.w;
        }
        float e = acc0 + acc1;
        float mx = e;
#pragma unroll
        for (int off = 16; off >= 1; off >>= 1)
            mx = fmaxf(mx, __shfl_xor_sync(0xffffffffu, mx, off));
        if (lane == 0) redm[warp] = mx;
        __syncthreads();
        mx = fmaxf(fmaxf(redm[q * 4], redm[q * 4 + 1]),
                   fmaxf(redm[q * 4 + 2], redm[q * 4 + 3]));
        float ex = __expf(e - mx);
        float sm = ex;
#pragma unroll
        for (int off = 16; off >= 1; off >>= 1)
            sm += __shfl_xor_sync(0xffffffffu, sm, off);
        if (lane == 0) reds[warp] = sm;
        __syncthreads();
        sm = reds[q * 4] + reds[q * 4 + 1] + reds[q * 4 + 2] + reds[q * 4 + 3];
        float alpha = ex / sm;
        int tau = tau0 + ti * 4 + q;
        size_t oi = ((size_t)b * T_ + tau) * N_ + n;
        out[oi] = alpha * x[oi];
        __syncthreads();
    }
}

extern "C" void kernel_launch(void* const* d_in, const int* in_sizes, int n_in,
                              void* d_out, int out_size) {
    const float* x  = (const float*)d_in[0];
    const float* s  = (const float*)d_in[1];
    const float* h  = (const float*)d_in[2];
    const float* We = (const float*)d_in[3];
    const float* Ue = (const float*)d_in[4];
    const float* ve = (const float*)d_in[5];
    const float* Wk = (const float*)d_in[6];
    const float* Wr = (const float*)d_in[7];
    const float* bb = (const float*)d_in[8];
    float* out = (float*)d_out;
    (void)in_sizes; (void)n_in; (void)out_size;

    float *xk_p, *r1_p;
    cudaGetSymbolAddress((void**)&xk_p, g_Xk);
    cudaGetSymbolAddress((void**)&r1_p, g_R1);
    __nv_bfloat16 *xs_hi, *xs_lo, *wk_hi, *wk_lo, *we_hi, *we_lo, *hs_hi, *hs_lo;
    cudaGetSymbolAddress((void**)&xs_hi, g_xs_hi);
    cudaGetSymbolAddress((void**)&xs_lo, g_xs_lo);
    cudaGetSymbolAddress((void**)&wk_hi, g_wkT_hi);
    cudaGetSymbolAddress((void**)&wk_lo, g_wkT_lo);
    cudaGetSymbolAddress((void**)&we_hi, g_weT_hi);
    cudaGetSymbolAddress((void**)&we_lo, g_weT_lo);
    cudaGetSymbolAddress((void**)&hs_hi, g_hs_hi);
    cudaGetSymbolAddress((void**)&hs_lo, g_hs_lo);

    k_init<<<1024, 256>>>(s, h);
    k_split<<<65536, 256>>>(x, Wk, We, Wr);
    k_r2<<<dim3(B_, 4), 256>>>(x, Ue);

    const int SMG = 4 * 128 * SSTR * 2;
    cudaFuncSetAttribute(k_gemm, cudaFuncAttributeMaxDynamicSharedMemorySize, SMG);
    k_gemm<<<dim3(1024, 8), 256, SMG>>>(xs_hi, xs_lo, wk_hi, wk_lo, 128, 1, bb, xk_p, 1);

    const int SML = (2 * 128 * WSTR + 2 * 32 * WSTR) * 2 + 32 * CSTR * 4;  // 185856
    cudaFuncSetAttribute(k_lstm_mma, cudaFuncAttributeMaxDynamicSharedMemorySize, SML);
    k_lstm_mma<<<GRID_LSTM, 256, SML>>>(s);

    k_gemm<<<dim3(1024, 2), 256, SMG>>>(hs_hi, hs_lo, we_hi, we_lo, 512, 4,
                                        (const float*)nullptr, r1_p, 0);

    const int SME = 128 * 260 * (int)sizeof(float);
    cudaFuncSetAttribute(k_e, cudaFuncAttributeMaxDynamicSharedMemorySize, SME);
    k_e<<<dim3(B_, 8), 512, SME>>>(x, ve, out);
}

// round 15
// speedup vs baseline: 1.7971x; 1.1304x over previous
#include <cuda_runtime.h>
#include <cuda_bf16.h>
#include <math.h>
#include <stdint.h>

#define B_ 512
#define T_ 256
#define N_ 128
#define M_ 256
#define FM_ 1024
#define GRID_LSTM 128

__device__ float g_r2[(size_t)B_ * N_ * T_];
__device__ float g_Xk[(size_t)T_ * B_ * FM_];
__device__ float g_R1[(size_t)T_ * B_ * T_];
__device__ unsigned long long g_arr[16];

__device__ __align__(16) __nv_bfloat16 g_xs_hi[(size_t)B_ * T_ * N_];
__device__ __align__(16) __nv_bfloat16 g_xs_lo[(size_t)B_ * T_ * N_];
__device__ __align__(16) __nv_bfloat16 g_wkT_hi[(size_t)FM_ * N_];
__device__ __align__(16) __nv_bfloat16 g_wkT_lo[(size_t)FM_ * N_];
__device__ __align__(16) __nv_bfloat16 g_weT_hi[(size_t)T_ * 2 * M_];
__device__ __align__(16) __nv_bfloat16 g_weT_lo[(size_t)T_ * 2 * M_];
__device__ __align__(16) __nv_bfloat16 g_hs_hi[(size_t)T_ * B_ * 2 * M_];
__device__ __align__(16) __nv_bfloat16 g_hs_lo[(size_t)T_ * B_ * 2 * M_];
__device__ __align__(16) __nv_bfloat16 g_wrT_hi[(size_t)FM_ * M_];
__device__ __align__(16) __nv_bfloat16 g_wrT_lo[(size_t)FM_ * M_];

__device__ __forceinline__ float sigm(float x) {
    return __fdividef(1.0f, 1.0f + __expf(-x));
}
__device__ __forceinline__ float tanh_e(float x) {
    float a = fabsf(x);
    float e = __expf(-2.0f * a);
    float r = __fdividef(1.0f - e, 1.0f + e);
    return copysignf(r, x);
}
__device__ __forceinline__ float tanh_fast(float x) {
    float y;
    asm("tanh.approx.f32 %0, %1;" : "=f"(y) : "f"(x));
    return y;
}
__device__ __forceinline__ void bsplit(float x, __nv_bfloat16& hi, __nv_bfloat16& lo) {
    hi = __float2bfloat16(x);
    lo = __float2bfloat16(x - __bfloat162float(hi));
}

#define MMA16816(c, a, b) \
    asm volatile("mma.sync.aligned.m16n8k16.row.col.f32.bf16.bf16.f32 " \
        "{%0,%1,%2,%3}, {%4,%5,%6,%7}, {%8,%9}, {%0,%1,%2,%3};" \
        : "+f"((c)[0]), "+f"((c)[1]), "+f"((c)[2]), "+f"((c)[3]) \
        : "r"((a)[0]), "r"((a)[1]), "r"((a)[2]), "r"((a)[3]), \
          "r"((b)[0]), "r"((b)[1]))

// ---- init: hs slot0, reset barriers ----
__global__ void k_init(const float* __restrict__ s, const float* __restrict__ h) {
    int i = blockIdx.x * blockDim.x + threadIdx.x;
    if (i < B_ * M_) {
        int b = i >> 8, m = i & 255;
        __nv_bfloat16 hi, lo;
        bsplit(h[i], hi, lo);
        g_hs_hi[(size_t)b * 512 + m] = hi;
        g_hs_lo[(size_t)b * 512 + m] = lo;
        bsplit(s[i], hi, lo);
        g_hs_hi[(size_t)b * 512 + 256 + m] = hi;
        g_hs_lo[(size_t)b * 512 + 256 + m] = lo;
    }
    if (i < 16) g_arr[i] = 0ull;
}

// ---- split x / WkT / WeT / WrT(gate-interleaved) into bf16 hi+lo ----
__global__ void k_split(const float* __restrict__ x, const float* __restrict__ Wk,
                        const float* __restrict__ We, const float* __restrict__ Wr) {
    size_t i = (size_t)blockIdx.x * blockDim.x + threadIdx.x;
    __nv_bfloat16 hi, lo;
    if (i < (size_t)B_ * T_ * N_) {
        bsplit(x[i], hi, lo);
        g_xs_hi[i] = hi;
        g_xs_lo[i] = lo;
    }
    if (i < (size_t)N_ * FM_) {
        int k = (int)(i >> 10), n = (int)(i & 1023);
        bsplit(Wk[i], hi, lo);
        g_wkT_hi[(size_t)n * 128 + k] = hi;
        g_wkT_lo[(size_t)n * 128 + k] = lo;
    }
    if (i < (size_t)2 * M_ * T_) {
        int k = (int)(i >> 8), u = (int)(i & 255);
        bsplit(We[i], hi, lo);
        g_weT_hi[(size_t)u * 512 + k] = hi;
        g_weT_lo[(size_t)u * 512 + k] = lo;
    }
    if (i < (size_t)M_ * FM_) {
        int k = (int)(i >> 10), c = (int)(i & 1023);
        int g = c >> 8, m = c & 255;
        int col2 = (m >> 5) * 128 + (m & 31) * 4 + g;
        bsplit(Wr[i], hi, lo);
        g_wrT_hi[(size_t)col2 * 256 + k] = hi;
        g_wrT_lo[(size_t)col2 * 256 + k] = lo;
    }
}

// ---- A-reuse split-bf16 HMMA GEMM ----
// block tile 64 rows x 256 cols (8 warps: wm 0..1 x wn 0..3, warp tile 32x64).
// NCP col passes (B restaged per pass, L2-resident); NKB K-chunks (acc across).
#define SSTR 136
template <int NKB, int NCP, int MODE>
__global__ __launch_bounds__(256, 1)
void k_gemm2(const __nv_bfloat16* __restrict__ Ah, const __nv_bfloat16* __restrict__ Al,
             const __nv_bfloat16* __restrict__ Bh, const __nv_bfloat16* __restrict__ Bl,
             int lda, const float* __restrict__ bias, float* __restrict__ Cout) {
    extern __shared__ __nv_bfloat16 smg[];
    __nv_bfloat16* ash = smg;                       // [64][SSTR]
    __nv_bfloat16* asl = ash + 64 * SSTR;
    __nv_bfloat16* bsh = asl + 64 * SSTR;           // [256][SSTR]
    __nv_bfloat16* bsl = bsh + 256 * SSTR;
    int tid = threadIdx.x, l = tid & 31, w = tid >> 5;
    int wm = w & 1, wn = w >> 1;
    int rb = blockIdx.x;
    int gr = l >> 2, tg = l & 3;

    for (int cp = 0; cp < NCP; cp++) {
        float acc[2][8][4];
#pragma unroll
        for (int mt = 0; mt < 2; mt++)
#pragma unroll
            for (int nt = 0; nt < 8; nt++)
#pragma unroll
                for (int j = 0; j < 4; j++) acc[mt][nt][j] = 0.f;

        for (int kb = 0; kb < NKB; kb++) {
            if (!(NKB == 1 && cp > 0)) {
#pragma unroll
                for (int i = 0; i < 4; i++) {
                    int idx = i * 256 + tid;
                    int r = idx >> 4, c = (idx & 15) * 8;
                    *(uint4*)&ash[r * SSTR + c] =
                        *(const uint4*)&Ah[(size_t)(rb * 64 + r) * lda + kb * 128 + c];
                    *(uint4*)&asl[r * SSTR + c] =
                        *(const uint4*)&Al[(size_t)(rb * 64 + r) * lda + kb * 128 + c];
                }
            }
#pragma unroll
            for (int i = 0; i < 16; i++) {
                int idx = i * 256 + tid;
                int r = idx >> 4, c = (idx & 15) * 8;
                *(uint4*)&bsh[r * SSTR + c] =
                    *(const uint4*)&Bh[(size_t)(cp * 256 + r) * lda + kb * 128 + c];
                *(uint4*)&bsl[r * SSTR + c] =
                    *(const uint4*)&Bl[(size_t)(cp * 256 + r) * lda + kb * 128 + c];
            }
            __syncthreads();
#pragma unroll
            for (int ks = 0; ks < 8; ks++) {
                int k0 = ks * 16;
                uint32_t ah[2][4], al[2][4];
#pragma unroll
                for (int mt = 0; mt < 2; mt++) {
                    int r = wm * 32 + mt * 16 + gr;
                    int c = k0 + tg * 2;
                    ah[mt][0] = *(uint32_t*)&ash[r * SSTR + c];
                    ah[mt][1] = *(uint32_t*)&ash[(r + 8) * SSTR + c];
                    ah[mt][2] = *(uint32_t*)&ash[r * SSTR + c + 8];
                    ah[mt][3] = *(uint32_t*)&ash[(r + 8) * SSTR + c + 8];
                    al[mt][0] = *(uint32_t*)&asl[r * SSTR + c];
                    al[mt][1] = *(uint32_t*)&asl[(r + 8) * SSTR + c];
                    al[mt][2] = *(uint32_t*)&asl[r * SSTR + c + 8];
                    al[mt][3] = *(uint32_t*)&asl[(r + 8) * SSTR + c + 8];
                }
#pragma unroll
                for (int nt = 0; nt < 8; nt++) {
                    int n = wn * 64 + nt * 8 + gr;
                    int kk = k0 + tg * 2;
                    uint32_t bh[2], bl2[2];
                    bh[0] = *(uint32_t*)&bsh[n * SSTR + kk];
                    bh[1] = *(uint32_t*)&bsh[n * SSTR + kk + 8];
                    bl2[0] = *(uint32_t*)&bsl[n * SSTR + kk];
                    bl2[1] = *(uint32_t*)&bsl[n * SSTR + kk + 8];
#pragma unroll
                    for (int mt = 0; mt < 2; mt++) {
                        MMA16816(acc[mt][nt], ah[mt], bh);
                        MMA16816(acc[mt][nt], ah[mt], bl2);
                        MMA16816(acc[mt][nt], al[mt], bh);
                    }
                }
            }
            __syncthreads();
        }
        // epilogue for this col pass
#pragma unroll
        for (int mt = 0; mt < 2; mt++)
#pragma unroll
            for (int nt = 0; nt < 8; nt++) {
                int row = rb * 64 + wm * 32 + mt * 16 + gr;
                int col = cp * 256 + wn * 64 + nt * 8 + tg * 2;
#pragma unroll
                for (int hf = 0; hf < 2; hf++) {
                    int rr = row + hf * 8;
                    float v0 = acc[mt][nt][hf * 2 + 0];
                    float v1 = acc[mt][nt][hf * 2 + 1];
                    if (MODE == 1) {
                        v0 += bias[col];
                        v1 += bias[col + 1];
                        int b = rr >> 8, t = rr & 255;
                        *(float2*)&Cout[((size_t)t * 512 + b) * 1024 + col] =
                            make_float2(v0, v1);
                    } else {
                        *(float2*)&Cout[(size_t)rr * 256 + col] = make_float2(v0, v1);
                    }
                }
            }
    }
}

// ---- persistent LSTM with HMMA; A staged directly from split hs ----
#define WSTR 264
#define CSTR 132
__global__ __launch_bounds__(256, 1) void k_lstm_mma(const float* __restrict__ s_in) {
    extern __shared__ char smc[];
    __nv_bfloat16* wbh = (__nv_bfloat16*)smc;             // [128][WSTR]
    __nv_bfloat16* wbl = wbh + 128 * WSTR;
    __nv_bfloat16* ahh = wbl + 128 * WSTR;                // [32][WSTR]
    __nv_bfloat16* ahl = ahh + 32 * WSTR;
    float* cs = (float*)(ahl + 32 * WSTR);                // [32][CSTR]

    int tid = threadIdx.x, l = tid & 31, w = tid >> 5;
    int bx = blockIdx.x >> 3, by = blockIdx.x & 7;
    int wm = w & 1, wn = w >> 1;
    int gr = l >> 2, tg = l & 3;
    int ml = tid & 31, rg = tid >> 5;
    int mg = by * 32 + ml;

#pragma unroll
    for (int i = 0; i < 16; i++) {
        int idx = i * 256 + tid;
        int c = idx >> 5, kc = (idx & 31) * 8;
        *(uint4*)&wbh[c * WSTR + kc] =
            *(const uint4*)&g_wrT_hi[(size_t)(by * 128 + c) * 256 + kc];
        *(uint4*)&wbl[c * WSTR + kc] =
            *(const uint4*)&g_wrT_lo[(size_t)(by * 128 + c) * 256 + kc];
    }

    float s4[4], px[4][4];
#pragma unroll
    for (int i = 0; i < 4; i++) {
        int b = bx * 32 + rg * 4 + i;
        s4[i] = s_in[(size_t)b * 256 + mg];
        size_t xo = (size_t)b * FM_ + mg;
        px[i][0] = g_Xk[xo];
        px[i][1] = g_Xk[xo + 256];
        px[i][2] = g_Xk[xo + 512];
        px[i][3] = g_Xk[xo + 768];
    }
    __syncthreads();

    for (int t = 0; t < T_; t++) {
        // stage A: 32 rows x 256 m, directly from split hs (h part = cols 0..255)
#pragma unroll
        for (int j = 0; j < 4; j++) {
            int idx = j * 256 + tid;
            int r = idx >> 5, m0 = (idx & 31) * 8;
            size_t ga = ((size_t)t * 512 + bx * 32 + r) * 512 + m0;
            *(uint4*)&ahh[r * WSTR + m0] = *(const uint4*)&g_hs_hi[ga];
            *(uint4*)&ahl[r * WSTR + m0] = *(const uint4*)&g_hs_lo[ga];
        }
        __syncthreads();

        float acc[4][4];
#pragma unroll
        for (int nt = 0; nt < 4; nt++)
#pragma unroll
            for (int j = 0; j < 4; j++) acc[nt][j] = 0.f;
#pragma unroll
        for (int ks = 0; ks < 16; ks++) {
            int k0 = ks * 16;
            int ar = wm * 16 + gr;
            int c = k0 + tg * 2;
            uint32_t ah[4], al[4];
            ah[0] = *(uint32_t*)&ahh[ar * WSTR + c];
            ah[1] = *(uint32_t*)&ahh[(ar + 8) * WSTR + c];
            ah[2] = *(uint32_t*)&ahh[ar * WSTR + c + 8];
            ah[3] = *(uint32_t*)&ahh[(ar + 8) * WSTR + c + 8];
            al[0] = *(uint32_t*)&ahl[ar * WSTR + c];
            al[1] = *(uint32_t*)&ahl[(ar + 8) * WSTR + c];
            al[2] = *(uint32_t*)&ahl[ar * WSTR + c + 8];
            al[3] = *(uint32_t*)&ahl[(ar + 8) * WSTR + c + 8];
#pragma unroll
            for (int nt = 0; nt < 4; nt++) {
                int bc = wn * 32 + nt * 8 + gr;
                uint32_t bh[2], bl2[2];
                bh[0] = *(uint32_t*)&wbh[bc * WSTR + c];
                bh[1] = *(uint32_t*)&wbh[bc * WSTR + c + 8];
                bl2[0] = *(uint32_t*)&wbl[bc * WSTR + c];
                bl2[1] = *(uint32_t*)&wbl[bc * WSTR + c + 8];
                MMA16816(acc[nt], ah, bh);
                MMA16816(acc[nt], ah, bl2);
                MMA16816(acc[nt], al, bh);
            }
        }
#pragma unroll
        for (int nt = 0; nt < 4; nt++) {
            int row = wm * 16 + gr;
            int col = wn * 32 + nt * 8 + tg * 2;
            *(float2*)&cs[row * CSTR + col] = make_float2(acc[nt][0], acc[nt][1]);
            *(float2*)&cs[(row + 8) * CSTR + col] = make_float2(acc[nt][2], acc[nt][3]);
        }
        __syncthreads();

#pragma unroll
        for (int i = 0; i < 4; i++) {
            int r = rg * 4 + i;
            int b = bx * 32 + r;
            float4 z4 = *(float4*)&cs[r * CSTR + ml * 4];
            float zi = z4.x + px[i][0];
            float zf = z4.y + px[i][1];
            float zg = z4.z + px[i][2];
            float zo = z4.w + px[i][3];
            float ig = sigm(zi), fg = sigm(zf), og = sigm(zo);
            float gg = tanh_e(zg);
            float sn = fg * s4[i] + ig * gg;
            float hn = og * tanh_e(sn);
            s4[i] = sn;
            if (t < 255) {
                size_t ra = ((size_t)(t + 1) * 512 + b) * 512;
                __nv_bfloat16 hi, lo;
                bsplit(hn, hi, lo);
                g_hs_hi[ra + mg] = hi;
                g_hs_lo[ra + mg] = lo;
                bsplit(sn, hi, lo);
                g_hs_hi[ra + 256 + mg] = hi;
                g_hs_lo[ra + 256 + mg] = lo;
            }
        }
        if (t == 255) break;
        int tn = t + 1;
#pragma unroll
        for (int i = 0; i < 4; i++) {
            int b = bx * 32 + rg * 4 + i;
            size_t xo = ((size_t)tn * B_ + b) * FM_ + mg;
            px[i][0] = g_Xk[xo];
            px[i][1] = g_Xk[xo + 256];
            px[i][2] = g_Xk[xo + 512];
            px[i][3] = g_Xk[xo + 768];
        }
        __syncthreads();
        if (tid == 0) {
            __threadfence();
            atomicAdd(&g_arr[bx], 1ull);
        }
        unsigned long long tgt = 8ull * (unsigned long long)(t + 1);
        while (*((volatile unsigned long long*)&g_arr[bx]) < tgt) {}
        __syncthreads();
    }
}

// ---- r2 (unchanged) ----
__global__ __launch_bounds__(256) void k_r2(const float* __restrict__ x,
                                            const float* __restrict__ Ue) {
    int b = blockIdx.x;
    int ut = blockIdx.y * 64;
    __shared__ float xs[32][128];
    __shared__ float us[32][64];
    int tid = threadIdx.x;
    int n0 = (tid & 31) * 4;
    int u0 = (tid >> 5) * 8;
    float acc[8][4];
#pragma unroll
    for (int j = 0; j < 8; j++)
#pragma unroll
        for (int i = 0; i < 4; i++) acc[j][i] = 0.f;
    for (int kt = 0; kt < T_; kt += 32) {
#pragma unroll
        for (int l = 0; l < 4; l++) {
            int idx = l * 256 + tid;
            int t = idx >> 5, n4 = idx & 31;
            *(float4*)&xs[t][n4 * 4] =
                ((const float4*)x)[(size_t)(b * T_ + kt + t) * 32 + n4];
        }
#pragma unroll
        for (int l = 0; l < 2; l++) {
            int idx = l * 256 + tid;
            int t = idx >> 4, u4 = idx & 15;
            *(float4*)&us[t][u4 * 4] =
                ((const float4*)Ue)[(size_t)(kt + t) * 64 + (ut >> 2) + u4];
        }
        __syncthreads();
#pragma unroll 8
        for (int k = 0; k < 32; k++) {
            float4 x4 = *(const float4*)&xs[k][n0];
            float4 ua = *(const float4*)&us[k][u0];
            float4 ub = *(const float4*)&us[k][u0 + 4];
            float xv[4] = {x4.x, x4.y, x4.z, x4.w};
            float uu[8] = {ua.x, ua.y, ua.z, ua.w, ub.x, ub.y, ub.z, ub.w};
#pragma unroll
            for (int j = 0; j < 8; j++)
#pragma unroll
                for (int i = 0; i < 4; i++) acc[j][i] += xv[i] * uu[j];
        }
        __syncthreads();
    }
#pragma unroll
    for (int i = 0; i < 4; i++) {
        size_t base = ((size_t)(b * N_ + n0 + i)) * T_ + ut + u0;
        *(float4*)&g_r2[base] = make_float4(acc[0][i], acc[1][i], acc[2][i], acc[3][i]);
        *(float4*)&g_r2[base + 4] = make_float4(acc[4][i], acc[5][i], acc[6][i], acc[7][i]);
    }
}

// ---- fused e/softmax/output (unchanged) ----
__global__ __launch_bounds__(512) void k_e(const float* __restrict__ x,
                                           const float* __restrict__ ve,
                                           float* __restrict__ out) {
    extern __shared__ float r2s[];
    __shared__ float r1s[4][256];
    __shared__ float ves[256];
    __shared__ float redm[16];
    __shared__ float reds[16];
    int b = blockIdx.x;
    int tau0 = blockIdx.y * 32;
    int tid = threadIdx.x;
    int lane = tid & 31;
    int warp = tid >> 5;
    int q = tid >> 7;
    int n = tid & 127;

    if (tid < 256) ves[tid] = ve[tid];
#pragma unroll
    for (int l = 0; l < 16; l++) {
        int idx = l * 512 + tid;
        int nn = idx >> 6, u4 = idx & 63;
        float4 v = ((const float4*)g_r2)[(size_t)(b * N_ + nn) * 64 + u4];
        *(float4*)&r2s[nn * 260 + u4 * 4] = v;
    }
    __syncthreads();
    const float* rp = &r2s[n * 260];

    for (int ti = 0; ti < 8; ti++) {
#pragma unroll
        for (int l = 0; l < 2; l++) {
            int idx = l * 512 + tid;
            int wh = idx >> 8, u = idx & 255;
            r1s[wh][u] = g_R1[((size_t)(tau0 + ti * 4 + wh) * B_ + b) * T_ + u];
        }
        __syncthreads();
        const float* r1p = r1s[q];
        float acc0 = 0.f, acc1 = 0.f;
#pragma unroll 4
        for (int u4 = 0; u4 < 64; u4++) {
            float4 rv = *(const float4*)&rp[u4 * 4];
            float4 r1 = *(const float4*)&r1p[u4 * 4];
            float4 vv = *(const float4*)&ves[u4 * 4];
            acc0 += tanh_fast(r1.x + rv.x) * vv.x;
            acc1 += tanh_fast(r1.y + rv.y) * vv.y;
            acc0 += tanh_fast(r1.z + rv.z) * vv.z;
            acc1 += tanh_fast(r1.w + rv.w) * vv.w;
        }
        float e = acc0 + acc1;
        float mx = e;
#pragma unroll
        for (int off = 16; off >= 1; off >>= 1)
            mx = fmaxf(mx, __shfl_xor_sync(0xffffffffu, mx, off));
        if (lane == 0) redm[warp] = mx;
        __syncthreads();
        mx = fmaxf(fmaxf(redm[q * 4], redm[q * 4 + 1]),
                   fmaxf(redm[q * 4 + 2], redm[q * 4 + 3]));
        float ex = __expf(e - mx);
        float sm = ex;
#pragma unroll
        for (int off = 16; off >= 1; off >>= 1)
            sm += __shfl_xor_sync(0xffffffffu, sm, off);
        if (lane == 0) reds[warp] = sm;
        __syncthreads();
        sm = reds[q * 4] + reds[q * 4 + 1] + reds[q * 4 + 2] + reds[q * 4 + 3];
        float alpha = ex / sm;
        int tau = tau0 + ti * 4 + q;
        size_t oi = ((size_t)b * T_ + tau) * N_ + n;
        out[oi] = alpha * x[oi];
        __syncthreads();
    }
}

extern "C" void kernel_launch(void* const* d_in, const int* in_sizes, int n_in,
                              void* d_out, int out_size) {
    const float* x  = (const float*)d_in[0];
    const float* s  = (const float*)d_in[1];
    const float* h  = (const float*)d_in[2];
    const float* We = (const float*)d_in[3];
    const float* Ue = (const float*)d_in[4];
    const float* ve = (const float*)d_in[5];
    const float* Wk = (const float*)d_in[6];
    const float* Wr = (const float*)d_in[7];
    const float* bb = (const float*)d_in[8];
    float* out = (float*)d_out;
    (void)in_sizes; (void)n_in; (void)out_size;

    float *xk_p, *r1_p;
    cudaGetSymbolAddress((void**)&xk_p, g_Xk);
    cudaGetSymbolAddress((void**)&r1_p, g_R1);
    __nv_bfloat16 *xs_hi, *xs_lo, *wk_hi, *wk_lo, *we_hi, *we_lo, *hs_hi, *hs_lo;
    cudaGetSymbolAddress((void**)&xs_hi, g_xs_hi);
    cudaGetSymbolAddress((void**)&xs_lo, g_xs_lo);
    cudaGetSymbolAddress((void**)&wk_hi, g_wkT_hi);
    cudaGetSymbolAddress((void**)&wk_lo, g_wkT_lo);
    cudaGetSymbolAddress((void**)&we_hi, g_weT_hi);
    cudaGetSymbolAddress((void**)&we_lo, g_weT_lo);
    cudaGetSymbolAddress((void**)&hs_hi, g_hs_hi);
    cudaGetSymbolAddress((void**)&hs_lo, g_hs_lo);

    k_init<<<1024, 256>>>(s, h);
    k_split<<<65536, 256>>>(x, Wk, We, Wr);
    k_r2<<<dim3(B_, 4), 256>>>(x, Ue);

    const int SMG2 = (64 + 64 + 256 + 256) * SSTR * 2;  // 174080
    cudaFuncSetAttribute(k_gemm2<1, 4, 1>,
                         cudaFuncAttributeMaxDynamicSharedMemorySize, SMG2);
    cudaFuncSetAttribute(k_gemm2<4, 1, 0>,
                         cudaFuncAttributeMaxDynamicSharedMemorySize, SMG2);
    k_gemm2<1, 4, 1><<<2048, 256, SMG2>>>(xs_hi, xs_lo, wk_hi, wk_lo, 128, bb, xk_p);

    const int SML = (2 * 128 * WSTR + 2 * 32 * WSTR) * 2 + 32 * CSTR * 4;
    cudaFuncSetAttribute(k_lstm_mma, cudaFuncAttributeMaxDynamicSharedMemorySize, SML);
    k_lstm_mma<<<GRID_LSTM, 256, SML>>>(s);

    k_gemm2<4, 1, 0><<<2048, 256, SMG2>>>(hs_hi, hs_lo, we_hi, we_lo, 512,
                                          (const float*)nullptr, r1_p);

    const int SME = 128 * 260 * (int)sizeof(float);
    cudaFuncSetAttribute(k_e, cudaFuncAttributeMaxDynamicSharedMemorySize, SME);
    k_e<<<dim3(B_, 8), 512, SME>>>(x, ve, out);
}

// round 16
// speedup vs baseline: 1.9132x; 1.0646x over previous
#include <cuda_runtime.h>
#include <cuda_bf16.h>
#include <cuda_fp16.h>
#include <math.h>
#include <stdint.h>

#define B_ 512
#define T_ 256
#define N_ 128
#define M_ 256
#define FM_ 1024
#define GRID_LSTM 128

__device__ float g_r2[(size_t)B_ * N_ * T_];
__device__ float g_Xk[(size_t)T_ * B_ * FM_];
__device__ float g_R1[(size_t)T_ * B_ * T_];
__device__ unsigned long long g_arr[16];

__device__ __align__(16) __nv_bfloat16 g_xs_hi[(size_t)B_ * T_ * N_];
__device__ __align__(16) __nv_bfloat16 g_xs_lo[(size_t)B_ * T_ * N_];
__device__ __align__(16) __nv_bfloat16 g_wkT_hi[(size_t)FM_ * N_];
__device__ __align__(16) __nv_bfloat16 g_wkT_lo[(size_t)FM_ * N_];
__device__ __align__(16) __nv_bfloat16 g_weT_hi[(size_t)T_ * 2 * M_];
__device__ __align__(16) __nv_bfloat16 g_weT_lo[(size_t)T_ * 2 * M_];
__device__ __align__(16) __nv_bfloat16 g_hs_hi[(size_t)T_ * B_ * 2 * M_];
__device__ __align__(16) __nv_bfloat16 g_hs_lo[(size_t)T_ * B_ * 2 * M_];
__device__ __align__(16) __nv_bfloat16 g_wrT_hi[(size_t)FM_ * M_];
__device__ __align__(16) __nv_bfloat16 g_wrT_lo[(size_t)FM_ * M_];

__device__ __forceinline__ float sigm(float x) {
    return __fdividef(1.0f, 1.0f + __expf(-x));
}
__device__ __forceinline__ float tanh_e(float x) {
    float a = fabsf(x);
    float e = __expf(-2.0f * a);
    float r = __fdividef(1.0f - e, 1.0f + e);
    return copysignf(r, x);
}
__device__ __forceinline__ void bsplit(float x, __nv_bfloat16& hi, __nv_bfloat16& lo) {
    hi = __float2bfloat16(x);
    lo = __float2bfloat16(x - __bfloat162float(hi));
}
// pack two fp32 -> f16x2 reg (lo = first PTX? first src = HIGH half)
__device__ __forceinline__ uint32_t pkh2(float lo, float hi) {
    uint32_t d;
    asm("cvt.rn.f16x2.f32 %0, %1, %2;" : "=r"(d) : "f"(hi), "f"(lo));
    return d;
}
__device__ __forceinline__ uint32_t tanh_h2(uint32_t z) {
    uint32_t d;
    asm("tanh.approx.f16x2 %0, %1;" : "=r"(d) : "r"(z));
    return d;
}

#define MMA16816(c, a, b) \
    asm volatile("mma.sync.aligned.m16n8k16.row.col.f32.bf16.bf16.f32 " \
        "{%0,%1,%2,%3}, {%4,%5,%6,%7}, {%8,%9}, {%0,%1,%2,%3};" \
        : "+f"((c)[0]), "+f"((c)[1]), "+f"((c)[2]), "+f"((c)[3]) \
        : "r"((a)[0]), "r"((a)[1]), "r"((a)[2]), "r"((a)[3]), \
          "r"((b)[0]), "r"((b)[1]))
#define MMAF16(c, a0, a1, a2, a3, b0, b1) \
    asm volatile("mma.sync.aligned.m16n8k16.row.col.f32.f16.f16.f32 " \
        "{%0,%1,%2,%3}, {%4,%5,%6,%7}, {%8,%9}, {%0,%1,%2,%3};" \
        : "+f"((c)[0]), "+f"((c)[1]), "+f"((c)[2]), "+f"((c)[3]) \
        : "r"(a0), "r"(a1), "r"(a2), "r"(a3), "r"(b0), "r"(b1))

// ---- init: hs slot0, reset barriers ----
__global__ void k_init(const float* __restrict__ s, const float* __restrict__ h) {
    int i = blockIdx.x * blockDim.x + threadIdx.x;
    if (i < B_ * M_) {
        int b = i >> 8, m = i & 255;
        __nv_bfloat16 hi, lo;
        bsplit(h[i], hi, lo);
        g_hs_hi[(size_t)b * 512 + m] = hi;
        g_hs_lo[(size_t)b * 512 + m] = lo;
        bsplit(s[i], hi, lo);
        g_hs_hi[(size_t)b * 512 + 256 + m] = hi;
        g_hs_lo[(size_t)b * 512 + 256 + m] = lo;
    }
    if (i < 16) g_arr[i] = 0ull;
}

// ---- split x / WkT / WeT / WrT(gate-interleaved) into bf16 hi+lo ----
__global__ void k_split(const float* __restrict__ x, const float* __restrict__ Wk,
                        const float* __restrict__ We, const float* __restrict__ Wr) {
    size_t i = (size_t)blockIdx.x * blockDim.x + threadIdx.x;
    __nv_bfloat16 hi, lo;
    if (i < (size_t)B_ * T_ * N_) {
        bsplit(x[i], hi, lo);
        g_xs_hi[i] = hi;
        g_xs_lo[i] = lo;
    }
    if (i < (size_t)N_ * FM_) {
        int k = (int)(i >> 10), n = (int)(i & 1023);
        bsplit(Wk[i], hi, lo);
        g_wkT_hi[(size_t)n * 128 + k] = hi;
        g_wkT_lo[(size_t)n * 128 + k] = lo;
    }
    if (i < (size_t)2 * M_ * T_) {
        int k = (int)(i >> 8), u = (int)(i & 255);
        bsplit(We[i], hi, lo);
        g_weT_hi[(size_t)u * 512 + k] = hi;
        g_weT_lo[(size_t)u * 512 + k] = lo;
    }
    if (i < (size_t)M_ * FM_) {
        int k = (int)(i >> 10), c = (int)(i & 1023);
        int g = c >> 8, m = c & 255;
        int col2 = (m >> 5) * 128 + (m & 31) * 4 + g;
        bsplit(Wr[i], hi, lo);
        g_wrT_hi[(size_t)col2 * 256 + k] = hi;
        g_wrT_lo[(size_t)col2 * 256 + k] = lo;
    }
}

// ---- A-reuse split-bf16 HMMA GEMM (R15, validated) ----
#define SSTR 136
template <int NKB, int NCP, int MODE>
__global__ __launch_bounds__(256, 1)
void k_gemm2(const __nv_bfloat16* __restrict__ Ah, const __nv_bfloat16* __restrict__ Al,
             const __nv_bfloat16* __restrict__ Bh, const __nv_bfloat16* __restrict__ Bl,
             int lda, const float* __restrict__ bias, float* __restrict__ Cout) {
    extern __shared__ __nv_bfloat16 smg[];
    __nv_bfloat16* ash = smg;
    __nv_bfloat16* asl = ash + 64 * SSTR;
    __nv_bfloat16* bsh = asl + 64 * SSTR;
    __nv_bfloat16* bsl = bsh + 256 * SSTR;
    int tid = threadIdx.x, l = tid & 31, w = tid >> 5;
    int wm = w & 1, wn = w >> 1;
    int rb = blockIdx.x;
    int gr = l >> 2, tg = l & 3;

    for (int cp = 0; cp < NCP; cp++) {
        float acc[2][8][4];
#pragma unroll
        for (int mt = 0; mt < 2; mt++)
#pragma unroll
            for (int nt = 0; nt < 8; nt++)
#pragma unroll
                for (int j = 0; j < 4; j++) acc[mt][nt][j] = 0.f;

        for (int kb = 0; kb < NKB; kb++) {
            if (!(NKB == 1 && cp > 0)) {
#pragma unroll
                for (int i = 0; i < 4; i++) {
                    int idx = i * 256 + tid;
                    int r = idx >> 4, c = (idx & 15) * 8;
                    *(uint4*)&ash[r * SSTR + c] =
                        *(const uint4*)&Ah[(size_t)(rb * 64 + r) * lda + kb * 128 + c];
                    *(uint4*)&asl[r * SSTR + c] =
                        *(const uint4*)&Al[(size_t)(rb * 64 + r) * lda + kb * 128 + c];
                }
            }
#pragma unroll
            for (int i = 0; i < 16; i++) {
                int idx = i * 256 + tid;
                int r = idx >> 4, c = (idx & 15) * 8;
                *(uint4*)&bsh[r * SSTR + c] =
                    *(const uint4*)&Bh[(size_t)(cp * 256 + r) * lda + kb * 128 + c];
                *(uint4*)&bsl[r * SSTR + c] =
                    *(const uint4*)&Bl[(size_t)(cp * 256 + r) * lda + kb * 128 + c];
            }
            __syncthreads();
#pragma unroll
            for (int ks = 0; ks < 8; ks++) {
                int k0 = ks * 16;
                uint32_t ah[2][4], al[2][4];
#pragma unroll
                for (int mt = 0; mt < 2; mt++) {
                    int r = wm * 32 + mt * 16 + gr;
                    int c = k0 + tg * 2;
                    ah[mt][0] = *(uint32_t*)&ash[r * SSTR + c];
                    ah[mt][1] = *(uint32_t*)&ash[(r + 8) * SSTR + c];
                    ah[mt][2] = *(uint32_t*)&ash[r * SSTR + c + 8];
                    ah[mt][3] = *(uint32_t*)&ash[(r + 8) * SSTR + c + 8];
                    al[mt][0] = *(uint32_t*)&asl[r * SSTR + c];
                    al[mt][1] = *(uint32_t*)&asl[(r + 8) * SSTR + c];
                    al[mt][2] = *(uint32_t*)&asl[r * SSTR + c + 8];
                    al[mt][3] = *(uint32_t*)&asl[(r + 8) * SSTR + c + 8];
                }
#pragma unroll
                for (int nt = 0; nt < 8; nt++) {
                    int n = wn * 64 + nt * 8 + gr;
                    int kk = k0 + tg * 2;
                    uint32_t bh[2], bl2[2];
                    bh[0] = *(uint32_t*)&bsh[n * SSTR + kk];
                    bh[1] = *(uint32_t*)&bsh[n * SSTR + kk + 8];
                    bl2[0] = *(uint32_t*)&bsl[n * SSTR + kk];
                    bl2[1] = *(uint32_t*)&bsl[n * SSTR + kk + 8];
#pragma unroll
                    for (int mt = 0; mt < 2; mt++) {
                        MMA16816(acc[mt][nt], ah[mt], bh);
                        MMA16816(acc[mt][nt], ah[mt], bl2);
                        MMA16816(acc[mt][nt], al[mt], bh);
                    }
                }
            }
            __syncthreads();
        }
#pragma unroll
        for (int mt = 0; mt < 2; mt++)
#pragma unroll
            for (int nt = 0; nt < 8; nt++) {
                int row = rb * 64 + wm * 32 + mt * 16 + gr;
                int col = cp * 256 + wn * 64 + nt * 8 + tg * 2;
#pragma unroll
                for (int hf = 0; hf < 2; hf++) {
                    int rr = row + hf * 8;
                    float v0 = acc[mt][nt][hf * 2 + 0];
                    float v1 = acc[mt][nt][hf * 2 + 1];
                    if (MODE == 1) {
                        v0 += bias[col];
                        v1 += bias[col + 1];
                        int b = rr >> 8, t = rr & 255;
                        *(float2*)&Cout[((size_t)t * 512 + b) * 1024 + col] =
                            make_float2(v0, v1);
                    } else {
                        *(float2*)&Cout[(size_t)rr * 256 + col] = make_float2(v0, v1);
                    }
                }
            }
    }
}

// ---- persistent LSTM with HMMA (R15, validated) ----
#define WSTR 264
#define CSTR 132
__global__ __launch_bounds__(256, 1) void k_lstm_mma(const float* __restrict__ s_in) {
    extern __shared__ char smc[];
    __nv_bfloat16* wbh = (__nv_bfloat16*)smc;
    __nv_bfloat16* wbl = wbh + 128 * WSTR;
    __nv_bfloat16* ahh = wbl + 128 * WSTR;
    __nv_bfloat16* ahl = ahh + 32 * WSTR;
    float* cs = (float*)(ahl + 32 * WSTR);

    int tid = threadIdx.x, l = tid & 31, w = tid >> 5;
    int bx = blockIdx.x >> 3, by = blockIdx.x & 7;
    int wm = w & 1, wn = w >> 1;
    int gr = l >> 2, tg = l & 3;
    int ml = tid & 31, rg = tid >> 5;
    int mg = by * 32 + ml;

#pragma unroll
    for (int i = 0; i < 16; i++) {
        int idx = i * 256 + tid;
        int c = idx >> 5, kc = (idx & 31) * 8;
        *(uint4*)&wbh[c * WSTR + kc] =
            *(const uint4*)&g_wrT_hi[(size_t)(by * 128 + c) * 256 + kc];
        *(uint4*)&wbl[c * WSTR + kc] =
            *(const uint4*)&g_wrT_lo[(size_t)(by * 128 + c) * 256 + kc];
    }

    float s4[4], px[4][4];
#pragma unroll
    for (int i = 0; i < 4; i++) {
        int b = bx * 32 + rg * 4 + i;
        s4[i] = s_in[(size_t)b * 256 + mg];
        size_t xo = (size_t)b * FM_ + mg;
        px[i][0] = g_Xk[xo];
        px[i][1] = g_Xk[xo + 256];
        px[i][2] = g_Xk[xo + 512];
        px[i][3] = g_Xk[xo + 768];
    }
    __syncthreads();

    for (int t = 0; t < T_; t++) {
#pragma unroll
        for (int j = 0; j < 4; j++) {
            int idx = j * 256 + tid;
            int r = idx >> 5, m0 = (idx & 31) * 8;
            size_t ga = ((size_t)t * 512 + bx * 32 + r) * 512 + m0;
            *(uint4*)&ahh[r * WSTR + m0] = *(const uint4*)&g_hs_hi[ga];
            *(uint4*)&ahl[r * WSTR + m0] = *(const uint4*)&g_hs_lo[ga];
        }
        __syncthreads();

        float acc[4][4];
#pragma unroll
        for (int nt = 0; nt < 4; nt++)
#pragma unroll
            for (int j = 0; j < 4; j++) acc[nt][j] = 0.f;
#pragma unroll
        for (int ks = 0; ks < 16; ks++) {
            int k0 = ks * 16;
            int ar = wm * 16 + gr;
            int c = k0 + tg * 2;
            uint32_t ah[4], al[4];
            ah[0] = *(uint32_t*)&ahh[ar * WSTR + c];
            ah[1] = *(uint32_t*)&ahh[(ar + 8) * WSTR + c];
            ah[2] = *(uint32_t*)&ahh[ar * WSTR + c + 8];
            ah[3] = *(uint32_t*)&ahh[(ar + 8) * WSTR + c + 8];
            al[0] = *(uint32_t*)&ahl[ar * WSTR + c];
            al[1] = *(uint32_t*)&ahl[(ar + 8) * WSTR + c];
            al[2] = *(uint32_t*)&ahl[ar * WSTR + c + 8];
            al[3] = *(uint32_t*)&ahl[(ar + 8) * WSTR + c + 8];
#pragma unroll
            for (int nt = 0; nt < 4; nt++) {
                int bc = wn * 32 + nt * 8 + gr;
                uint32_t bh[2], bl2[2];
                bh[0] = *(uint32_t*)&wbh[bc * WSTR + c];
                bh[1] = *(uint32_t*)&wbh[bc * WSTR + c + 8];
                bl2[0] = *(uint32_t*)&wbl[bc * WSTR + c];
                bl2[1] = *(uint32_t*)&wbl[bc * WSTR + c + 8];
                MMA16816(acc[nt], ah, bh);
                MMA16816(acc[nt], ah, bl2);
                MMA16816(acc[nt], al, bh);
            }
        }
#pragma unroll
        for (int nt = 0; nt < 4; nt++) {
            int row = wm * 16 + gr;
            int col = wn * 32 + nt * 8 + tg * 2;
            *(float2*)&cs[row * CSTR + col] = make_float2(acc[nt][0], acc[nt][1]);
            *(float2*)&cs[(row + 8) * CSTR + col] = make_float2(acc[nt][2], acc[nt][3]);
        }
        __syncthreads();

#pragma unroll
        for (int i = 0; i < 4; i++) {
            int r = rg * 4 + i;
            int b = bx * 32 + r;
            float4 z4 = *(float4*)&cs[r * CSTR + ml * 4];
            float zi = z4.x + px[i][0];
            float zf = z4.y + px[i][1];
            float zg = z4.z + px[i][2];
            float zo = z4.w + px[i][3];
            float ig = sigm(zi), fg = sigm(zf), og = sigm(zo);
            float gg = tanh_e(zg);
            float sn = fg * s4[i] + ig * gg;
            float hn = og * tanh_e(sn);
            s4[i] = sn;
            if (t < 255) {
                size_t ra = ((size_t)(t + 1) * 512 + b) * 512;
                __nv_bfloat16 hi, lo;
                bsplit(hn, hi, lo);
                g_hs_hi[ra + mg] = hi;
                g_hs_lo[ra + mg] = lo;
                bsplit(sn, hi, lo);
                g_hs_hi[ra + 256 + mg] = hi;
                g_hs_lo[ra + 256 + mg] = lo;
            }
        }
        if (t == 255) break;
        int tn = t + 1;
#pragma unroll
        for (int i = 0; i < 4; i++) {
            int b = bx * 32 + rg * 4 + i;
            size_t xo = ((size_t)tn * B_ + b) * FM_ + mg;
            px[i][0] = g_Xk[xo];
            px[i][1] = g_Xk[xo + 256];
            px[i][2] = g_Xk[xo + 512];
            px[i][3] = g_Xk[xo + 768];
        }
        __syncthreads();
        if (tid == 0) {
            __threadfence();
            atomicAdd(&g_arr[bx], 1ull);
        }
        unsigned long long tgt = 8ull * (unsigned long long)(t + 1);
        while (*((volatile unsigned long long*)&g_arr[bx]) < tgt) {}
        __syncthreads();
    }
}

// ---- r2 (unchanged) ----
__global__ __launch_bounds__(256) void k_r2(const float* __restrict__ x,
                                            const float* __restrict__ Ue) {
    int b = blockIdx.x;
    int ut = blockIdx.y * 64;
    __shared__ float xs[32][128];
    __shared__ float us[32][64];
    int tid = threadIdx.x;
    int n0 = (tid & 31) * 4;
    int u0 = (tid >> 5) * 8;
    float acc[8][4];
#pragma unroll
    for (int j = 0; j < 8; j++)
#pragma unroll
        for (int i = 0; i < 4; i++) acc[j][i] = 0.f;
    for (int kt = 0; kt < T_; kt += 32) {
#pragma unroll
        for (int l = 0; l < 4; l++) {
            int idx = l * 256 + tid;
            int t = idx >> 5, n4 = idx & 31;
            *(float4*)&xs[t][n4 * 4] =
                ((const float4*)x)[(size_t)(b * T_ + kt + t) * 32 + n4];
        }
#pragma unroll
        for (int l = 0; l < 2; l++) {
            int idx = l * 256 + tid;
            int t = idx >> 4, u4 = idx & 15;
            *(float4*)&us[t][u4 * 4] =
                ((const float4*)Ue)[(size_t)(kt + t) * 64 + (ut >> 2) + u4];
        }
        __syncthreads();
#pragma unroll 8
        for (int k = 0; k < 32; k++) {
            float4 x4 = *(const float4*)&xs[k][n0];
            float4 ua = *(const float4*)&us[k][u0];
            float4 ub = *(const float4*)&us[k][u0 + 4];
            float xv[4] = {x4.x, x4.y, x4.z, x4.w};
            float uu[8] = {ua.x, ua.y, ua.z, ua.w, ub.x, ub.y, ub.z, ub.w};
#pragma unroll
            for (int j = 0; j < 8; j++)
#pragma unroll
                for (int i = 0; i < 4; i++) acc[j][i] += xv[i] * uu[j];
        }
        __syncthreads();
    }
#pragma unroll
    for (int i = 0; i < 4; i++) {
        size_t base = ((size_t)(b * N_ + n0 + i)) * T_ + ut + u0;
        *(float4*)&g_r2[base] = make_float4(acc[0][i], acc[1][i], acc[2][i], acc[3][i]);
        *(float4*)&g_r2[base + 4] = make_float4(acc[4][i], acc[5][i], acc[6][i], acc[7][i]);
    }
}

// ---- k_e2: tanh.f16x2 + HMMA dot. Per block: 1 b, 32 tau, 128 n. ----
// warp w owns tau pair (2w, 2w+1); mma rows = 2tau x 8n; k-slots permuted so
// each lane's 4 u are contiguous (one LDS.128 per operand).
#define R2STR 272
__global__ __launch_bounds__(512) void k_e2(const float* __restrict__ x,
                                            const float* __restrict__ ve,
                                            float* __restrict__ out) {
    extern __shared__ char sme[];
    float* r2s = (float*)sme;                       // [128][R2STR]
    float* r1s = r2s + 128 * R2STR;                 // [32][256]
    float* es = r1s + 32 * 256;                     // [32][128]
    uint32_t* vesh = (uint32_t*)(es + 32 * 128);    // [128] half2
    int b = blockIdx.x;
    int tau0 = blockIdx.y * 32;
    int tid = threadIdx.x, lane = tid & 31, w = tid >> 5;
    int gr = lane >> 2, tg = lane & 3;

    if (tid < 128) {
        __half2 v = __floats2half2_rn(ve[tid * 2], ve[tid * 2 + 1]);
        vesh[tid] = *(uint32_t*)&v;
    }
#pragma unroll
    for (int l = 0; l < 16; l++) {
        int idx = l * 512 + tid;
        int nn = idx >> 6, u4 = (idx & 63) * 4;
        *(float4*)&r2s[nn * R2STR + u4] =
            *(const float4*)&g_r2[((size_t)(b * N_ + nn)) * 256 + u4];
    }
#pragma unroll
    for (int l = 0; l < 4; l++) {
        int idx = l * 512 + tid;
        int tt = idx >> 6, u4 = (idx & 63) * 4;
        *(float4*)&r1s[tt * 256 + u4] =
            *(const float4*)&g_R1[((size_t)(tau0 + tt) * B_ + b) * 256 + u4];
    }
    __syncthreads();

    int ta = 2 * w, tb = 2 * w + 1;
    const float* r1a = &r1s[ta * 256];
    const float* r1b = &r1s[tb * 256];
#pragma unroll 1
    for (int g = 0; g < 16; g++) {
        int n = g * 8 + gr;
        const float* rp = &r2s[n * R2STR];
        float c[4] = {0.f, 0.f, 0.f, 0.f};
#pragma unroll 4
        for (int uc = 0; uc < 16; uc++) {
            int u = uc * 16 + tg * 4;
            float4 r2v = *(const float4*)&rp[u];
            float4 va = *(const float4*)&r1a[u];
            float4 vb = *(const float4*)&r1b[u];
            uint32_t a0 = tanh_h2(pkh2(r2v.x + va.x, r2v.y + va.y));
            uint32_t a2 = tanh_h2(pkh2(r2v.z + va.z, r2v.w + va.w));
            uint32_t a1 = tanh_h2(pkh2(r2v.x + vb.x, r2v.y + vb.y));
            uint32_t a3 = tanh_h2(pkh2(r2v.z + vb.z, r2v.w + vb.w));
            uint32_t b0 = vesh[(u >> 1)];
            uint32_t b1 = vesh[(u >> 1) + 1];
            MMAF16(c, a0, a1, a2, a3, b0, b1);
        }
        if (tg == 0) {
            es[ta * 128 + n] = c[0];
            es[tb * 128 + n] = c[2];
        }
    }
    __syncwarp();

#pragma unroll
    for (int tt = 0; tt < 2; tt++) {
        int tau = 2 * w + tt;
        float e0 = es[tau * 128 + lane];
        float e1 = es[tau * 128 + lane + 32];
        float e2 = es[tau * 128 + lane + 64];
        float e3 = es[tau * 128 + lane + 96];
        float mx = fmaxf(fmaxf(e0, e1), fmaxf(e2, e3));
#pragma unroll
        for (int off = 16; off >= 1; off >>= 1)
            mx = fmaxf(mx, __shfl_xor_sync(0xffffffffu, mx, off));
        float x0 = __expf(e0 - mx), x1 = __expf(e1 - mx);
        float x2 = __expf(e2 - mx), x3 = __expf(e3 - mx);
        float sm = x0 + x1 + x2 + x3;
#pragma unroll
        for (int off = 16; off >= 1; off >>= 1)
            sm += __shfl_xor_sync(0xffffffffu, sm, off);
        float inv = __fdividef(1.0f, sm);
        size_t base = ((size_t)b * T_ + tau0 + tau) * N_;
        out[base + lane] = x0 * inv * x[base + lane];
        out[base + lane + 32] = x1 * inv * x[base + lane + 32];
        out[base + lane + 64] = x2 * inv * x[base + lane + 64];
        out[base + lane + 96] = x3 * inv * x[base + lane + 96];
    }
}

extern "C" void kernel_launch(void* const* d_in, const int* in_sizes, int n_in,
                              void* d_out, int out_size) {
    const float* x  = (const float*)d_in[0];
    const float* s  = (const float*)d_in[1];
    const float* h  = (const float*)d_in[2];
    const float* We = (const float*)d_in[3];
    const float* Ue = (const float*)d_in[4];
    const float* ve = (const float*)d_in[5];
    const float* Wk = (const float*)d_in[6];
    const float* Wr = (const float*)d_in[7];
    const float* bb = (const float*)d_in[8];
    float* out = (float*)d_out;
    (void)in_sizes; (void)n_in; (void)out_size;

    float *xk_p, *r1_p;
    cudaGetSymbolAddress((void**)&xk_p, g_Xk);
    cudaGetSymbolAddress((void**)&r1_p, g_R1);
    __nv_bfloat16 *xs_hi, *xs_lo, *wk_hi, *wk_lo, *we_hi, *we_lo, *hs_hi, *hs_lo;
    cudaGetSymbolAddress((void**)&xs_hi, g_xs_hi);
    cudaGetSymbolAddress((void**)&xs_lo, g_xs_lo);
    cudaGetSymbolAddress((void**)&wk_hi, g_wkT_hi);
    cudaGetSymbolAddress((void**)&wk_lo, g_wkT_lo);
    cudaGetSymbolAddress((void**)&we_hi, g_weT_hi);
    cudaGetSymbolAddress((void**)&we_lo, g_weT_lo);
    cudaGetSymbolAddress((void**)&hs_hi, g_hs_hi);
    cudaGetSymbolAddress((void**)&hs_lo, g_hs_lo);

    k_init<<<1024, 256>>>(s, h);
    k_split<<<65536, 256>>>(x, Wk, We, Wr);
    k_r2<<<dim3(B_, 4), 256>>>(x, Ue);

    const int SMG2 = (64 + 64 + 256 + 256) * SSTR * 2;
    cudaFuncSetAttribute(k_gemm2<1, 4, 1>,
                         cudaFuncAttributeMaxDynamicSharedMemorySize, SMG2);
    cudaFuncSetAttribute(k_gemm2<4, 1, 0>,
                         cudaFuncAttributeMaxDynamicSharedMemorySize, SMG2);
    k_gemm2<1, 4, 1><<<2048, 256, SMG2>>>(xs_hi, xs_lo, wk_hi, wk_lo, 128, bb, xk_p);

    const int SML = (2 * 128 * WSTR + 2 * 32 * WSTR) * 2 + 32 * CSTR * 4;
    cudaFuncSetAttribute(k_lstm_mma, cudaFuncAttributeMaxDynamicSharedMemorySize, SML);
    k_lstm_mma<<<GRID_LSTM, 256, SML>>>(s);

    k_gemm2<4, 1, 0><<<2048, 256, SMG2>>>(hs_hi, hs_lo, we_hi, we_lo, 512,
                                          (const float*)nullptr, r1_p);

    const int SME2 = 128 * R2STR * 4 + 32 * 256 * 4 + 32 * 128 * 4 + 128 * 4;
    cudaFuncSetAttribute(k_e2, cudaFuncAttributeMaxDynamicSharedMemorySize, SME2);
    k_e2<<<dim3(B_, 8), 512, SME2>>>(x, ve, out);
}

// round 17
// speedup vs baseline: 1.9382x; 1.0131x over previous
#include <cuda_runtime.h>
#include <cuda_bf16.h>
#include <cuda_fp16.h>
#include <math.h>
#include <stdint.h>

#define B_ 512
#define T_ 256
#define N_ 128
#define M_ 256
#define FM_ 1024
#define GRID_LSTM 128

__device__ float g_r2[(size_t)B_ * N_ * T_];
__device__ float g_Xk[(size_t)T_ * B_ * FM_];
__device__ float g_R1[(size_t)T_ * B_ * T_];
__device__ unsigned long long g_arr[16];

__device__ __align__(16) __nv_bfloat16 g_xs_hi[(size_t)B_ * T_ * N_];
__device__ __align__(16) __nv_bfloat16 g_xs_lo[(size_t)B_ * T_ * N_];
__device__ __align__(16) __nv_bfloat16 g_wkT_hi[(size_t)FM_ * N_];
__device__ __align__(16) __nv_bfloat16 g_wkT_lo[(size_t)FM_ * N_];
__device__ __align__(16) __nv_bfloat16 g_weT_hi[(size_t)T_ * 2 * M_];
__device__ __align__(16) __nv_bfloat16 g_weT_lo[(size_t)T_ * 2 * M_];
__device__ __align__(16) __nv_bfloat16 g_hs_hi[(size_t)T_ * B_ * 2 * M_];
__device__ __align__(16) __nv_bfloat16 g_hs_lo[(size_t)T_ * B_ * 2 * M_];
__device__ __align__(16) __nv_bfloat16 g_wrT_hi[(size_t)FM_ * M_];
__device__ __align__(16) __nv_bfloat16 g_wrT_lo[(size_t)FM_ * M_];

__device__ __forceinline__ float sigm(float x) {
    return __fdividef(1.0f, 1.0f + __expf(-x));
}
__device__ __forceinline__ float tanh_e(float x) {
    float a = fabsf(x);
    float e = __expf(-2.0f * a);
    float r = __fdividef(1.0f - e, 1.0f + e);
    return copysignf(r, x);
}
__device__ __forceinline__ void bsplit(float x, __nv_bfloat16& hi, __nv_bfloat16& lo) {
    hi = __float2bfloat16(x);
    lo = __float2bfloat16(x - __bfloat162float(hi));
}
__device__ __forceinline__ uint32_t pkh2(float lo, float hi) {
    uint32_t d;
    asm("cvt.rn.f16x2.f32 %0, %1, %2;" : "=r"(d) : "f"(hi), "f"(lo));
    return d;
}
__device__ __forceinline__ uint32_t tanh_h2(uint32_t z) {
    uint32_t d;
    asm("tanh.approx.f16x2 %0, %1;" : "=r"(d) : "r"(z));
    return d;
}

#define MMA16816(c, a, b) \
    asm volatile("mma.sync.aligned.m16n8k16.row.col.f32.bf16.bf16.f32 " \
        "{%0,%1,%2,%3}, {%4,%5,%6,%7}, {%8,%9}, {%0,%1,%2,%3};" \
        : "+f"((c)[0]), "+f"((c)[1]), "+f"((c)[2]), "+f"((c)[3]) \
        : "r"((a)[0]), "r"((a)[1]), "r"((a)[2]), "r"((a)[3]), \
          "r"((b)[0]), "r"((b)[1]))
#define MMAF16(c, a0, a1, a2, a3, b0, b1) \
    asm volatile("mma.sync.aligned.m16n8k16.row.col.f32.f16.f16.f32 " \
        "{%0,%1,%2,%3}, {%4,%5,%6,%7}, {%8,%9}, {%0,%1,%2,%3};" \
        : "+f"((c)[0]), "+f"((c)[1]), "+f"((c)[2]), "+f"((c)[3]) \
        : "r"(a0), "r"(a1), "r"(a2), "r"(a3), "r"(b0), "r"(b1))

__global__ void k_init(const float* __restrict__ s, const float* __restrict__ h) {
    int i = blockIdx.x * blockDim.x + threadIdx.x;
    if (i < B_ * M_) {
        int b = i >> 8, m = i & 255;
        __nv_bfloat16 hi, lo;
        bsplit(h[i], hi, lo);
        g_hs_hi[(size_t)b * 512 + m] = hi;
        g_hs_lo[(size_t)b * 512 + m] = lo;
        bsplit(s[i], hi, lo);
        g_hs_hi[(size_t)b * 512 + 256 + m] = hi;
        g_hs_lo[(size_t)b * 512 + 256 + m] = lo;
    }
    if (i < 16) g_arr[i] = 0ull;
}

__global__ void k_split(const float* __restrict__ x, const float* __restrict__ Wk,
                        const float* __restrict__ We, const float* __restrict__ Wr) {
    size_t i = (size_t)blockIdx.x * blockDim.x + threadIdx.x;
    __nv_bfloat16 hi, lo;
    if (i < (size_t)B_ * T_ * N_) {
        bsplit(x[i], hi, lo);
        g_xs_hi[i] = hi;
        g_xs_lo[i] = lo;
    }
    if (i < (size_t)N_ * FM_) {
        int k = (int)(i >> 10), n = (int)(i & 1023);
        bsplit(Wk[i], hi, lo);
        g_wkT_hi[(size_t)n * 128 + k] = hi;
        g_wkT_lo[(size_t)n * 128 + k] = lo;
    }
    if (i < (size_t)2 * M_ * T_) {
        int k = (int)(i >> 8), u = (int)(i & 255);
        bsplit(We[i], hi, lo);
        g_weT_hi[(size_t)u * 512 + k] = hi;
        g_weT_lo[(size_t)u * 512 + k] = lo;
    }
    if (i < (size_t)M_ * FM_) {
        int k = (int)(i >> 10), c = (int)(i & 1023);
        int g = c >> 8, m = c & 255;
        int col2 = (m >> 5) * 128 + (m & 31) * 4 + g;
        bsplit(Wr[i], hi, lo);
        g_wrT_hi[(size_t)col2 * 256 + k] = hi;
        g_wrT_lo[(size_t)col2 * 256 + k] = lo;
    }
}

// ---- A-reuse split-bf16 HMMA GEMM (validated R15/R16) ----
#define SSTR 136
template <int NKB, int NCP, int MODE>
__global__ __launch_bounds__(256, 1)
void k_gemm2(const __nv_bfloat16* __restrict__ Ah, const __nv_bfloat16* __restrict__ Al,
             const __nv_bfloat16* __restrict__ Bh, const __nv_bfloat16* __restrict__ Bl,
             int lda, const float* __restrict__ bias, float* __restrict__ Cout) {
    extern __shared__ __nv_bfloat16 smg[];
    __nv_bfloat16* ash = smg;
    __nv_bfloat16* asl = ash + 64 * SSTR;
    __nv_bfloat16* bsh = asl + 64 * SSTR;
    __nv_bfloat16* bsl = bsh + 256 * SSTR;
    int tid = threadIdx.x, l = tid & 31, w = tid >> 5;
    int wm = w & 1, wn = w >> 1;
    int rb = blockIdx.x;
    int gr = l >> 2, tg = l & 3;

    for (int cp = 0; cp < NCP; cp++) {
        float acc[2][8][4];
#pragma unroll
        for (int mt = 0; mt < 2; mt++)
#pragma unroll
            for (int nt = 0; nt < 8; nt++)
#pragma unroll
                for (int j = 0; j < 4; j++) acc[mt][nt][j] = 0.f;

        for (int kb = 0; kb < NKB; kb++) {
            if (!(NKB == 1 && cp > 0)) {
#pragma unroll
                for (int i = 0; i < 4; i++) {
                    int idx = i * 256 + tid;
                    int r = idx >> 4, c = (idx & 15) * 8;
                    *(uint4*)&ash[r * SSTR + c] =
                        *(const uint4*)&Ah[(size_t)(rb * 64 + r) * lda + kb * 128 + c];
                    *(uint4*)&asl[r * SSTR + c] =
                        *(const uint4*)&Al[(size_t)(rb * 64 + r) * lda + kb * 128 + c];
                }
            }
#pragma unroll
            for (int i = 0; i < 16; i++) {
                int idx = i * 256 + tid;
                int r = idx >> 4, c = (idx & 15) * 8;
                *(uint4*)&bsh[r * SSTR + c] =
                    *(const uint4*)&Bh[(size_t)(cp * 256 + r) * lda + kb * 128 + c];
                *(uint4*)&bsl[r * SSTR + c] =
                    *(const uint4*)&Bl[(size_t)(cp * 256 + r) * lda + kb * 128 + c];
            }
            __syncthreads();
#pragma unroll
            for (int ks = 0; ks < 8; ks++) {
                int k0 = ks * 16;
                uint32_t ah[2][4], al[2][4];
#pragma unroll
                for (int mt = 0; mt < 2; mt++) {
                    int r = wm * 32 + mt * 16 + gr;
                    int c = k0 + tg * 2;
                    ah[mt][0] = *(uint32_t*)&ash[r * SSTR + c];
                    ah[mt][1] = *(uint32_t*)&ash[(r + 8) * SSTR + c];
                    ah[mt][2] = *(uint32_t*)&ash[r * SSTR + c + 8];
                    ah[mt][3] = *(uint32_t*)&ash[(r + 8) * SSTR + c + 8];
                    al[mt][0] = *(uint32_t*)&asl[r * SSTR + c];
                    al[mt][1] = *(uint32_t*)&asl[(r + 8) * SSTR + c];
                    al[mt][2] = *(uint32_t*)&asl[r * SSTR + c + 8];
                    al[mt][3] = *(uint32_t*)&asl[(r + 8) * SSTR + c + 8];
                }
#pragma unroll
                for (int nt = 0; nt < 8; nt++) {
                    int n = wn * 64 + nt * 8 + gr;
                    int kk = k0 + tg * 2;
                    uint32_t bh[2], bl2[2];
                    bh[0] = *(uint32_t*)&bsh[n * SSTR + kk];
                    bh[1] = *(uint32_t*)&bsh[n * SSTR + kk + 8];
                    bl2[0] = *(uint32_t*)&bsl[n * SSTR + kk];
                    bl2[1] = *(uint32_t*)&bsl[n * SSTR + kk + 8];
#pragma unroll
                    for (int mt = 0; mt < 2; mt++) {
                        MMA16816(acc[mt][nt], ah[mt], bh);
                        MMA16816(acc[mt][nt], ah[mt], bl2);
                        MMA16816(acc[mt][nt], al[mt], bh);
                    }
                }
            }
            __syncthreads();
        }
#pragma unroll
        for (int mt = 0; mt < 2; mt++)
#pragma unroll
            for (int nt = 0; nt < 8; nt++) {
                int row = rb * 64 + wm * 32 + mt * 16 + gr;
                int col = cp * 256 + wn * 64 + nt * 8 + tg * 2;
#pragma unroll
                for (int hf = 0; hf < 2; hf++) {
                    int rr = row + hf * 8;
                    float v0 = acc[mt][nt][hf * 2 + 0];
                    float v1 = acc[mt][nt][hf * 2 + 1];
                    if (MODE == 1) {
                        v0 += bias[col];
                        v1 += bias[col + 1];
                        int b = rr >> 8, t = rr & 255;
                        *(float2*)&Cout[((size_t)t * 512 + b) * 1024 + col] =
                            make_float2(v0, v1);
                    } else {
                        *(float2*)&Cout[(size_t)rr * 256 + col] = make_float2(v0, v1);
                    }
                }
            }
    }
}

// ---- persistent LSTM with HMMA (validated R15/R16) ----
#define WSTR 264
#define CSTR 132
__global__ __launch_bounds__(256, 1) void k_lstm_mma(const float* __restrict__ s_in) {
    extern __shared__ char smc[];
    __nv_bfloat16* wbh = (__nv_bfloat16*)smc;
    __nv_bfloat16* wbl = wbh + 128 * WSTR;
    __nv_bfloat16* ahh = wbl + 128 * WSTR;
    __nv_bfloat16* ahl = ahh + 32 * WSTR;
    float* cs = (float*)(ahl + 32 * WSTR);

    int tid = threadIdx.x, l = tid & 31, w = tid >> 5;
    int bx = blockIdx.x >> 3, by = blockIdx.x & 7;
    int wm = w & 1, wn = w >> 1;
    int gr = l >> 2, tg = l & 3;
    int ml = tid & 31, rg = tid >> 5;
    int mg = by * 32 + ml;

#pragma unroll
    for (int i = 0; i < 16; i++) {
        int idx = i * 256 + tid;
        int c = idx >> 5, kc = (idx & 31) * 8;
        *(uint4*)&wbh[c * WSTR + kc] =
            *(const uint4*)&g_wrT_hi[(size_t)(by * 128 + c) * 256 + kc];
        *(uint4*)&wbl[c * WSTR + kc] =
            *(const uint4*)&g_wrT_lo[(size_t)(by * 128 + c) * 256 + kc];
    }

    float s4[4], px[4][4];
#pragma unroll
    for (int i = 0; i < 4; i++) {
        int b = bx * 32 + rg * 4 + i;
        s4[i] = s_in[(size_t)b * 256 + mg];
        size_t xo = (size_t)b * FM_ + mg;
        px[i][0] = g_Xk[xo];
        px[i][1] = g_Xk[xo + 256];
        px[i][2] = g_Xk[xo + 512];
        px[i][3] = g_Xk[xo + 768];
    }
    __syncthreads();

    for (int t = 0; t < T_; t++) {
#pragma unroll
        for (int j = 0; j < 4; j++) {
            int idx = j * 256 + tid;
            int r = idx >> 5, m0 = (idx & 31) * 8;
            size_t ga = ((size_t)t * 512 + bx * 32 + r) * 512 + m0;
            *(uint4*)&ahh[r * WSTR + m0] = *(const uint4*)&g_hs_hi[ga];
            *(uint4*)&ahl[r * WSTR + m0] = *(const uint4*)&g_hs_lo[ga];
        }
        __syncthreads();

        float acc[4][4];
#pragma unroll
        for (int nt = 0; nt < 4; nt++)
#pragma unroll
            for (int j = 0; j < 4; j++) acc[nt][j] = 0.f;
#pragma unroll
        for (int ks = 0; ks < 16; ks++) {
            int k0 = ks * 16;
            int ar = wm * 16 + gr;
            int c = k0 + tg * 2;
            uint32_t ah[4], al[4];
            ah[0] = *(uint32_t*)&ahh[ar * WSTR + c];
            ah[1] = *(uint32_t*)&ahh[(ar + 8) * WSTR + c];
            ah[2] = *(uint32_t*)&ahh[ar * WSTR + c + 8];
            ah[3] = *(uint32_t*)&ahh[(ar + 8) * WSTR + c + 8];
            al[0] = *(uint32_t*)&ahl[ar * WSTR + c];
            al[1] = *(uint32_t*)&ahl[(ar + 8) * WSTR + c];
            al[2] = *(uint32_t*)&ahl[ar * WSTR + c + 8];
            al[3] = *(uint32_t*)&ahl[(ar + 8) * WSTR + c + 8];
#pragma unroll
            for (int nt = 0; nt < 4; nt++) {
                int bc = wn * 32 + nt * 8 + gr;
                uint32_t bh[2], bl2[2];
                bh[0] = *(uint32_t*)&wbh[bc * WSTR + c];
                bh[1] = *(uint32_t*)&wbh[bc * WSTR + c + 8];
                bl2[0] = *(uint32_t*)&wbl[bc * WSTR + c];
                bl2[1] = *(uint32_t*)&wbl[bc * WSTR + c + 8];
                MMA16816(acc[nt], ah, bh);
                MMA16816(acc[nt], ah, bl2);
                MMA16816(acc[nt], al, bh);
            }
        }
#pragma unroll
        for (int nt = 0; nt < 4; nt++) {
            int row = wm * 16 + gr;
            int col = wn * 32 + nt * 8 + tg * 2;
            *(float2*)&cs[row * CSTR + col] = make_float2(acc[nt][0], acc[nt][1]);
            *(float2*)&cs[(row + 8) * CSTR + col] = make_float2(acc[nt][2], acc[nt][3]);
        }
        __syncthreads();

#pragma unroll
        for (int i = 0; i < 4; i++) {
            int r = rg * 4 + i;
            int b = bx * 32 + r;
            float4 z4 = *(float4*)&cs[r * CSTR + ml * 4];
            float zi = z4.x + px[i][0];
            float zf = z4.y + px[i][1];
            float zg = z4.z + px[i][2];
            float zo = z4.w + px[i][3];
            float ig = sigm(zi), fg = sigm(zf), og = sigm(zo);
            float gg = tanh_e(zg);
            float sn = fg * s4[i] + ig * gg;
            float hn = og * tanh_e(sn);
            s4[i] = sn;
            if (t < 255) {
                size_t ra = ((size_t)(t + 1) * 512 + b) * 512;
                __nv_bfloat16 hi, lo;
                bsplit(hn, hi, lo);
                g_hs_hi[ra + mg] = hi;
                g_hs_lo[ra + mg] = lo;
                bsplit(sn, hi, lo);
                g_hs_hi[ra + 256 + mg] = hi;
                g_hs_lo[ra + 256 + mg] = lo;
            }
        }
        if (t == 255) break;
        int tn = t + 1;
#pragma unroll
        for (int i = 0; i < 4; i++) {
            int b = bx * 32 + rg * 4 + i;
            size_t xo = ((size_t)tn * B_ + b) * FM_ + mg;
            px[i][0] = g_Xk[xo];
            px[i][1] = g_Xk[xo + 256];
            px[i][2] = g_Xk[xo + 512];
            px[i][3] = g_Xk[xo + 768];
        }
        __syncthreads();
        if (tid == 0) {
            __threadfence();
            atomicAdd(&g_arr[bx], 1ull);
        }
        unsigned long long tgt = 8ull * (unsigned long long)(t + 1);
        while (*((volatile unsigned long long*)&g_arr[bx]) < tgt) {}
        __syncthreads();
    }
}

// ---- r2 (unchanged, now on side stream) ----
__global__ __launch_bounds__(256) void k_r2(const float* __restrict__ x,
                                            const float* __restrict__ Ue) {
    int b = blockIdx.x;
    int ut = blockIdx.y * 64;
    __shared__ float xs[32][128];
    __shared__ float us[32][64];
    int tid = threadIdx.x;
    int n0 = (tid & 31) * 4;
    int u0 = (tid >> 5) * 8;
    float acc[8][4];
#pragma unroll
    for (int j = 0; j < 8; j++)
#pragma unroll
        for (int i = 0; i < 4; i++) acc[j][i] = 0.f;
    for (int kt = 0; kt < T_; kt += 32) {
#pragma unroll
        for (int l = 0; l < 4; l++) {
            int idx = l * 256 + tid;
            int t = idx >> 5, n4 = idx & 31;
            *(float4*)&xs[t][n4 * 4] =
                ((const float4*)x)[(size_t)(b * T_ + kt + t) * 32 + n4];
        }
#pragma unroll
        for (int l = 0; l < 2; l++) {
            int idx = l * 256 + tid;
            int t = idx >> 4, u4 = idx & 15;
            *(float4*)&us[t][u4 * 4] =
                ((const float4*)Ue)[(size_t)(kt + t) * 64 + (ut >> 2) + u4];
        }
        __syncthreads();
#pragma unroll 8
        for (int k = 0; k < 32; k++) {
            float4 x4 = *(const float4*)&xs[k][n0];
            float4 ua = *(const float4*)&us[k][u0];
            float4 ub = *(const float4*)&us[k][u0 + 4];
            float xv[4] = {x4.x, x4.y, x4.z, x4.w};
            float uu[8] = {ua.x, ua.y, ua.z, ua.w, ub.x, ub.y, ub.z, ub.w};
#pragma unroll
            for (int j = 0; j < 8; j++)
#pragma unroll
                for (int i = 0; i < 4; i++) acc[j][i] += xv[i] * uu[j];
        }
        __syncthreads();
    }
#pragma unroll
    for (int i = 0; i < 4; i++) {
        size_t base = ((size_t)(b * N_ + n0 + i)) * T_ + ut + u0;
        *(float4*)&g_r2[base] = make_float4(acc[0][i], acc[1][i], acc[2][i], acc[3][i]);
        *(float4*)&g_r2[base + 4] = make_float4(acc[4][i], acc[5][i], acc[6][i], acc[7][i]);
    }
}

// ---- k_e3: r2 block-resident, tau loop. grid (512 b, 2 halves), block 512. ----
#define R2STR 272
__global__ __launch_bounds__(512) void k_e3(const float* __restrict__ x,
                                            const float* __restrict__ ve,
                                            float* __restrict__ out) {
    extern __shared__ char sme[];
    float* r2s = (float*)sme;                       // [128][R2STR]
    float* r1s = r2s + 128 * R2STR;                 // [32][256]
    float* es = r1s + 32 * 256;                     // [32][128]
    uint32_t* vesh = (uint32_t*)(es + 32 * 128);    // [128] half2
    int b = blockIdx.x;
    int tid = threadIdx.x, lane = tid & 31, w = tid >> 5;
    int gr = lane >> 2, tg = lane & 3;

    if (tid < 128) {
        __half2 v = __floats2half2_rn(ve[tid * 2], ve[tid * 2 + 1]);
        vesh[tid] = *(uint32_t*)&v;
    }
#pragma unroll
    for (int l = 0; l < 16; l++) {
        int idx = l * 512 + tid;
        int nn = idx >> 6, u4 = (idx & 63) * 4;
        *(float4*)&r2s[nn * R2STR + u4] =
            *(const float4*)&g_r2[((size_t)(b * N_ + nn)) * 256 + u4];
    }

    for (int tc = 0; tc < 4; tc++) {
        int tau0 = blockIdx.y * 128 + tc * 32;
        __syncthreads();   // r1s safe to overwrite (and r2s/vesh visible on tc=0)
#pragma unroll
        for (int l = 0; l < 4; l++) {
            int idx = l * 512 + tid;
            int tt = idx >> 6, u4 = (idx & 63) * 4;
            *(float4*)&r1s[tt * 256 + u4] =
                *(const float4*)&g_R1[((size_t)(tau0 + tt) * B_ + b) * 256 + u4];
        }
        __syncthreads();

        int ta = 2 * w, tb = 2 * w + 1;
        const float* r1a = &r1s[ta * 256];
        const float* r1b = &r1s[tb * 256];
#pragma unroll 1
        for (int g = 0; g < 16; g++) {
            int n = g * 8 + gr;
            const float* rp = &r2s[n * R2STR];
            float c[4] = {0.f, 0.f, 0.f, 0.f};
#pragma unroll 4
            for (int uc = 0; uc < 16; uc++) {
                int u = uc * 16 + tg * 4;
                float4 r2v = *(const float4*)&rp[u];
                float4 va = *(const float4*)&r1a[u];
                float4 vb = *(const float4*)&r1b[u];
                uint32_t a0 = tanh_h2(pkh2(r2v.x + va.x, r2v.y + va.y));
                uint32_t a2 = tanh_h2(pkh2(r2v.z + va.z, r2v.w + va.w));
                uint32_t a1 = tanh_h2(pkh2(r2v.x + vb.x, r2v.y + vb.y));
                uint32_t a3 = tanh_h2(pkh2(r2v.z + vb.z, r2v.w + vb.w));
                uint32_t b0 = vesh[(u >> 1)];
                uint32_t b1 = vesh[(u >> 1) + 1];
                MMAF16(c, a0, a1, a2, a3, b0, b1);
            }
            if (tg == 0) {
                es[ta * 128 + n] = c[0];
                es[tb * 128 + n] = c[2];
            }
        }
        __syncwarp();

#pragma unroll
        for (int tt = 0; tt < 2; tt++) {
            int tau = tau0 + 2 * w + tt;
            int er = (2 * w + tt) * 128;
            float e0 = es[er + lane];
            float e1 = es[er + lane + 32];
            float e2 = es[er + lane + 64];
            float e3 = es[er + lane + 96];
            float mx = fmaxf(fmaxf(e0, e1), fmaxf(e2, e3));
#pragma unroll
            for (int off = 16; off >= 1; off >>= 1)
                mx = fmaxf(mx, __shfl_xor_sync(0xffffffffu, mx, off));
            float x0 = __expf(e0 - mx), x1 = __expf(e1 - mx);
            float x2 = __expf(e2 - mx), x3 = __expf(e3 - mx);
            float sm = x0 + x1 + x2 + x3;
#pragma unroll
            for (int off = 16; off >= 1; off >>= 1)
                sm += __shfl_xor_sync(0xffffffffu, sm, off);
            float inv = __fdividef(1.0f, sm);
            size_t base = ((size_t)b * T_ + tau) * N_;
            out[base + lane] = x0 * inv * x[base + lane];
            out[base + lane + 32] = x1 * inv * x[base + lane + 32];
            out[base + lane + 64] = x2 * inv * x[base + lane + 64];
            out[base + lane + 96] = x3 * inv * x[base + lane + 96];
        }
    }
}

extern "C" void kernel_launch(void* const* d_in, const int* in_sizes, int n_in,
                              void* d_out, int out_size) {
    const float* x  = (const float*)d_in[0];
    const float* s  = (const float*)d_in[1];
    const float* h  = (const float*)d_in[2];
    const float* We = (const float*)d_in[3];
    const float* Ue = (const float*)d_in[4];
    const float* ve = (const float*)d_in[5];
    const float* Wk = (const float*)d_in[6];
    const float* Wr = (const float*)d_in[7];
    const float* bb = (const float*)d_in[8];
    float* out = (float*)d_out;
    (void)in_sizes; (void)n_in; (void)out_size;

    float *xk_p, *r1_p;
    cudaGetSymbolAddress((void**)&xk_p, g_Xk);
    cudaGetSymbolAddress((void**)&r1_p, g_R1);
    __nv_bfloat16 *xs_hi, *xs_lo, *wk_hi, *wk_lo, *we_hi, *we_lo, *hs_hi, *hs_lo;
    cudaGetSymbolAddress((void**)&xs_hi, g_xs_hi);
    cudaGetSymbolAddress((void**)&xs_lo, g_xs_lo);
    cudaGetSymbolAddress((void**)&wk_hi, g_wkT_hi);
    cudaGetSymbolAddress((void**)&wk_lo, g_wkT_lo);
    cudaGetSymbolAddress((void**)&we_hi, g_weT_hi);
    cudaGetSymbolAddress((void**)&we_lo, g_weT_lo);
    cudaGetSymbolAddress((void**)&hs_hi, g_hs_hi);
    cudaGetSymbolAddress((void**)&hs_lo, g_hs_lo);

    // fork: k_r2 depends only on inputs; joined before k_e3
    static cudaStream_t s2 = nullptr;
    static cudaEvent_t evF = nullptr, evJ = nullptr;
    if (!s2) {
        cudaStreamCreateWithFlags(&s2, cudaStreamNonBlocking);
        cudaEventCreateWithFlags(&evF, cudaEventDisableTiming);
        cudaEventCreateWithFlags(&evJ, cudaEventDisableTiming);
    }
    cudaEventRecord(evF, 0);
    cudaStreamWaitEvent(s2, evF, 0);
    k_r2<<<dim3(B_, 4), 256, 0, s2>>>(x, Ue);
    cudaEventRecord(evJ, s2);

    k_init<<<1024, 256>>>(s, h);
    k_split<<<65536, 256>>>(x, Wk, We, Wr);

    const int SMG2 = (64 + 64 + 256 + 256) * SSTR * 2;
    cudaFuncSetAttribute(k_gemm2<1, 4, 1>,
                         cudaFuncAttributeMaxDynamicSharedMemorySize, SMG2);
    cudaFuncSetAttribute(k_gemm2<4, 1, 0>,
                         cudaFuncAttributeMaxDynamicSharedMemorySize, SMG2);
    k_gemm2<1, 4, 1><<<2048, 256, SMG2>>>(xs_hi, xs_lo, wk_hi, wk_lo, 128, bb, xk_p);

    const int SML = (2 * 128 * WSTR + 2 * 32 * WSTR) * 2 + 32 * CSTR * 4;
    cudaFuncSetAttribute(k_lstm_mma, cudaFuncAttributeMaxDynamicSharedMemorySize, SML);
    k_lstm_mma<<<GRID_LSTM, 256, SML>>>(s);

    k_gemm2<4, 1, 0><<<2048, 256, SMG2>>>(hs_hi, hs_lo, we_hi, we_lo, 512,
                                          (const float*)nullptr, r1_p);

    cudaStreamWaitEvent(0, evJ, 0);
    const int SME3 = 128 * R2STR * 4 + 32 * 256 * 4 + 32 * 128 * 4 + 128 * 4;
    cudaFuncSetAttribute(k_e3, cudaFuncAttributeMaxDynamicSharedMemorySize, SME3);
    k_e3<<<dim3(B_, 2), 512, SME3>>>(x, ve, out);
}